// round 1
// baseline (speedup 1.0000x reference)
#include <cuda_runtime.h>
#include <math.h>
#include <stdint.h>

// ---------------- problem constants (fixed shapes for this problem) ----------
constexpr int BB   = 8;      // batch
constexpr int SEQ  = 2048;   // tokens per utterance
constexpr int NWRD = 256;    // words per utterance
constexpr int DIM  = 768;    // model dim
constexpr int HID  = 768;    // GRU hidden
constexpr int TT   = 8;      // tokens per word (WLEN)
constexpr int NSEG = BB * NWRD;       // 2048 GRU sequences
constexpr int H3   = 3 * HID;         // 2304
constexpr int NTOT = NSEG * TT;       // 16384 rows for gi GEMMs
constexpr int FFD  = 3072;
constexpr int NHEAD= 4;
constexpr int DHD  = 192;
constexpr int NLAY = 3;

// ---------------- scratch (device globals; no cudaMalloc allowed) ------------
__device__ float g_s8  [TT * DIM];
__device__ float g_s256[NWRD * DIM];
__device__ float g_seg [(size_t)NTOT * DIM];
__device__ float g_gi  [2ull * NTOT * H3];     // per-direction input projections
__device__ float g_gh  [2ull * NSEG * H3];     // per-step hidden projections
__device__ float g_h   [2ull * NSEG * HID];    // GRU hidden state per dir
__device__ float g_y0  [(size_t)NTOT * 2 * HID];
__device__ float g_y1  [(size_t)NTOT * 2 * HID];
__device__ float g_xn  [(size_t)NSEG * DIM];
__device__ float g_qkv [3ull * NSEG * DIM];
__device__ float g_att [(size_t)BB * NHEAD * NWRD * NWRD];
__device__ float g_o   [(size_t)NSEG * DIM];
__device__ float g_ff  [(size_t)NSEG * FFD];

// ---------------- small helpers ----------------------------------------------
__device__ __forceinline__ float gelu_f(float x) {
    // jax.nn.gelu default (approximate=True, tanh form)
    float x3 = x * x * x;
    return 0.5f * x * (1.f + tanhf(0.7978845608028654f * (x + 0.044715f * x3)));
}
__device__ __forceinline__ float sigmoid_f(float x) {
    return 1.f / (1.f + expf(-x));
}

__global__ void zero_kernel(float* p, size_t n) {
    size_t i = (size_t)blockIdx.x * blockDim.x + threadIdx.x;
    if (i < n) p[i] = 0.f;
}

// Sinusoid tables computed in double to match numpy float64 table construction.
__global__ void sintab_kernel() {
    int idx = blockIdx.x * blockDim.x + threadIdx.x;
    const int total = (TT + NWRD) * DIM;
    if (idx >= total) return;
    int p = idx / DIM, d = idx % DIM;
    double e   = (double)(2 * (d / 2)) / (double)DIM;
    double den = pow(10000.0, e);
    int pos    = (p < TT) ? p : (p - TT);
    double ang = (double)pos / den;
    float v = (d & 1) ? (float)cos(ang) : (float)sin(ang);
    if (p < TT) g_s8[p * DIM + d] = v;
    else        g_s256[(p - TT) * DIM + d] = v;
}

// seg[n,t,d] = emb[x[n*8+t], d] + sin8[t,d]
__global__ void embed_kernel(const int* __restrict__ x, const float* __restrict__ emb) {
    size_t idx = (size_t)blockIdx.x * blockDim.x + threadIdx.x;
    if (idx >= (size_t)NTOT * DIM) return;
    int d  = (int)(idx % DIM);
    int nt = (int)(idx / DIM);
    int t  = nt % TT;
    int tok = x[nt];
    g_seg[idx] = emb[(size_t)tok * DIM + d] + g_s8[t * DIM + d];
}

// PyTorch GRU cell gates (r,z,n); batched over dir via index.
__global__ void gru_gate_kernel(const float* __restrict__ bih,
                                const float* __restrict__ bhh,
                                float* __restrict__ y, int step) {
    size_t idx = (size_t)blockIdx.x * blockDim.x + threadIdx.x;
    if (idx >= 2ull * NSEG * HID) return;
    int j   = (int)(idx % HID);
    int n   = (int)((idx / HID) % NSEG);
    int dir = (int)(idx / ((size_t)NSEG * HID));
    int t   = dir ? (TT - 1 - step) : step;

    const float* gp = g_gi + ((size_t)dir * NTOT + (size_t)n * TT + t) * H3;
    const float* hp = g_gh + ((size_t)dir * NSEG + n) * H3;
    const float* bi = bih + (size_t)dir * H3;
    const float* bh = bhh + (size_t)dir * H3;

    float r  = sigmoid_f(gp[j]           + bi[j]           + hp[j]           + bh[j]);
    float z  = sigmoid_f(gp[HID + j]     + bi[HID + j]     + hp[HID + j]     + bh[HID + j]);
    float ng = gp[2 * HID + j] + bi[2 * HID + j] + r * (hp[2 * HID + j] + bh[2 * HID + j]);

    float* hptr = g_h + ((size_t)dir * NSEG + n) * HID + j;
    float hn = (1.f - z) * tanhf(ng) + z * (*hptr);
    *hptr = hn;
    y[((size_t)n * TT + t) * (2 * HID) + (size_t)dir * HID + j] = hn;
}

// we = y1[:,0]+y1[:,-1], summed over direction halves; + bert_emb + sin256
__global__ void we_kernel(const float* __restrict__ bemb, float* __restrict__ out) {
    size_t idx = (size_t)blockIdx.x * blockDim.x + threadIdx.x;
    if (idx >= (size_t)NSEG * DIM) return;
    int d = (int)(idx % DIM);
    int n = (int)(idx / DIM);
    int w = n % NWRD;
    const float* y = g_y1 + (size_t)n * TT * 2 * HID;
    float v = y[d] + y[HID + d]
            + y[(TT - 1) * 2 * HID + d] + y[(TT - 1) * 2 * HID + HID + d];
    out[idx] = v + bemb[idx] + g_s256[(size_t)w * DIM + d];
}

// LayerNorm over 768, block per row, 256 threads (3 elems each)
__global__ void ln_kernel(const float* __restrict__ xin, const float* __restrict__ g,
                          const float* __restrict__ b, float* __restrict__ xo) {
    int row = blockIdx.x;
    const float* xr = xin + (size_t)row * DIM;
    float v[3], s = 0.f, s2 = 0.f;
    #pragma unroll
    for (int i = 0; i < 3; i++) {
        v[i] = xr[threadIdx.x + i * 256];
        s += v[i]; s2 += v[i] * v[i];
    }
    #pragma unroll
    for (int o = 16; o > 0; o >>= 1) {
        s  += __shfl_down_sync(0xffffffffu, s,  o);
        s2 += __shfl_down_sync(0xffffffffu, s2, o);
    }
    __shared__ float sa[8], sc[8];
    int w = threadIdx.x >> 5, l = threadIdx.x & 31;
    if (l == 0) { sa[w] = s; sc[w] = s2; }
    __syncthreads();
    if (threadIdx.x == 0) {
        float ta = 0.f, tc = 0.f;
        #pragma unroll
        for (int i = 0; i < 8; i++) { ta += sa[i]; tc += sc[i]; }
        sa[0] = ta; sc[0] = tc;
    }
    __syncthreads();
    float mean = sa[0] / DIM;
    float var  = sc[0] / DIM - mean * mean;
    float rstd = rsqrtf(var + 1e-6f);
    #pragma unroll
    for (int i = 0; i < 3; i++) {
        int d = threadIdx.x + i * 256;
        xo[(size_t)row * DIM + d] = (v[i] - mean) * rstd * g[d] + b[d];
    }
}

// softmax over 256 keys, one warp per row
__global__ void softmax_kernel(float* __restrict__ att) {
    int row = blockIdx.x * (blockDim.x / 32) + (threadIdx.x >> 5);
    if (row >= BB * NHEAD * NWRD) return;
    int l = threadIdx.x & 31;
    float* p = att + (size_t)row * NWRD;
    float v[8], m = -1e30f;
    #pragma unroll
    for (int i = 0; i < 8; i++) { v[i] = p[l + i * 32]; m = fmaxf(m, v[i]); }
    #pragma unroll
    for (int o = 16; o > 0; o >>= 1) m = fmaxf(m, __shfl_xor_sync(0xffffffffu, m, o));
    float s = 0.f;
    #pragma unroll
    for (int i = 0; i < 8; i++) { v[i] = expf(v[i] - m); s += v[i]; }
    #pragma unroll
    for (int o = 16; o > 0; o >>= 1) s += __shfl_xor_sync(0xffffffffu, s, o);
    float inv = 1.f / s;
    #pragma unroll
    for (int i = 0; i < 8; i++) p[l + i * 32] = v[i] * inv;
}

// ---------------- batched SGEMM: C = act(alpha*A@op(B) + bias) [+ C] ---------
// BT=true : B is [N,K] row-major (weights, NT).  BT=false: B is [K,N] (NN).
// Batching: per z-block, offset = (z/zdiv)*s?1 + (z%zdiv)*s?2.
template <bool BT, bool ACC, bool BIAS, bool GELUA>
__global__ void __launch_bounds__(256) sgemm_k(
    const float* __restrict__ A, const float* __restrict__ B,
    const float* __restrict__ bias, float* __restrict__ C,
    int M, int Nc, int K, int lda, int ldb, int ldc,
    int zdiv, long long sA1, long long sA2, long long sB1, long long sB2,
    long long sC1, long long sC2, long long sBias, float alpha)
{
    int z  = blockIdx.z;
    int z1 = z / zdiv, z2 = z % zdiv;
    A += z1 * sA1 + z2 * sA2;
    B += z1 * sB1 + z2 * sB2;
    C += z1 * sC1 + z2 * sC2;
    if (BIAS) bias += z1 * sBias;

    const int bm = blockIdx.y * 128, bn = blockIdx.x * 128;
    __shared__ float As[8][128];
    __shared__ float Bs[8][128];
    const int tid  = threadIdx.x;
    const int trow = tid / 16, tcol = tid % 16;
    float acc[8][8] = {};
    float ar[8], br[8];
    const int arow = tid >> 1, acol = (tid & 1) * 4;
    const int nbrow = tid >> 5, nbcol = (tid & 31) * 4;

    for (int k0 = 0; k0 < K; k0 += 8) {  // K % 8 == 0 for all call sites
        int gm = bm + arow;
        #pragma unroll
        for (int i = 0; i < 4; i++)
            As[acol + i][arow] = (gm < M) ? A[(size_t)gm * lda + k0 + acol + i] : 0.f;
        if (BT) {
            int gn = bn + arow;
            #pragma unroll
            for (int i = 0; i < 4; i++)
                Bs[acol + i][arow] = (gn < Nc) ? B[(size_t)gn * ldb + k0 + acol + i] : 0.f;
        } else {
            #pragma unroll
            for (int i = 0; i < 4; i++) {
                int gn = bn + nbcol + i;
                Bs[nbrow][nbcol + i] = (gn < Nc) ? B[(size_t)(k0 + nbrow) * ldb + gn] : 0.f;
            }
        }
        __syncthreads();
        #pragma unroll
        for (int kk = 0; kk < 8; kk++) {
            #pragma unroll
            for (int i = 0; i < 8; i++) ar[i] = As[kk][trow * 8 + i];
            #pragma unroll
            for (int j = 0; j < 8; j++) br[j] = Bs[kk][tcol * 8 + j];
            #pragma unroll
            for (int i = 0; i < 8; i++)
                #pragma unroll
                for (int j = 0; j < 8; j++)
                    acc[i][j] = fmaf(ar[i], br[j], acc[i][j]);
        }
        __syncthreads();
    }
    #pragma unroll
    for (int i = 0; i < 8; i++) {
        int m = bm + trow * 8 + i;
        if (m >= M) continue;
        #pragma unroll
        for (int j = 0; j < 8; j++) {
            int n = bn + tcol * 8 + j;
            if (n >= Nc) continue;
            float v = acc[i][j] * alpha;
            if (BIAS)  v += bias[n];
            if (GELUA) v = gelu_f(v);
            size_t off = (size_t)m * ldc + n;
            if (ACC) C[off] += v; else C[off] = v;
        }
    }
}

// host-side dispatch
enum GemmMode { GM_PLAIN = 0, GM_BIAS = 1, GM_ACCBIAS = 2, GM_BIASGELU = 3, GM_NN = 4 };

static void run_gemm(GemmMode mode,
                     const float* A, const float* B, const float* bias, float* C,
                     int M, int Nc, int K, int lda, int ldb, int ldc,
                     int batch, int zdiv,
                     long long sA1, long long sA2, long long sB1, long long sB2,
                     long long sC1, long long sC2, long long sBias, float alpha)
{
    dim3 grid((Nc + 127) / 128, (M + 127) / 128, batch);
    switch (mode) {
    case GM_PLAIN:
        sgemm_k<true, false, false, false><<<grid, 256>>>(A, B, bias, C, M, Nc, K, lda, ldb, ldc,
            zdiv, sA1, sA2, sB1, sB2, sC1, sC2, sBias, alpha); break;
    case GM_BIAS:
        sgemm_k<true, false, true, false><<<grid, 256>>>(A, B, bias, C, M, Nc, K, lda, ldb, ldc,
            zdiv, sA1, sA2, sB1, sB2, sC1, sC2, sBias, alpha); break;
    case GM_ACCBIAS:
        sgemm_k<true, true, true, false><<<grid, 256>>>(A, B, bias, C, M, Nc, K, lda, ldb, ldc,
            zdiv, sA1, sA2, sB1, sB2, sC1, sC2, sBias, alpha); break;
    case GM_BIASGELU:
        sgemm_k<true, false, true, true><<<grid, 256>>>(A, B, bias, C, M, Nc, K, lda, ldb, ldc,
            zdiv, sA1, sA2, sB1, sB2, sC1, sC2, sBias, alpha); break;
    case GM_NN:
        sgemm_k<false, false, false, false><<<grid, 256>>>(A, B, bias, C, M, Nc, K, lda, ldb, ldc,
            zdiv, sA1, sA2, sB1, sB2, sC1, sC2, sBias, alpha); break;
    }
}

static void run_zero(float* p, size_t n) {
    zero_kernel<<<(unsigned)((n + 255) / 256), 256>>>(p, n);
}

// ---------------- driver ------------------------------------------------------
extern "C" void kernel_launch(void* const* d_in, const int* in_sizes, int n_in,
                              void* d_out, int out_size)
{
    const int*   x    = (const int*)  d_in[0];
    // d_in[1] = gate_for_words (uniform segmentation, unused: WLEN fixed = 8)
    const float* bemb = (const float*)d_in[2];
    const float* emb  = (const float*)d_in[3];
    const float* wih0 = (const float*)d_in[4];
    const float* whh0 = (const float*)d_in[5];
    const float* bih0 = (const float*)d_in[6];
    const float* bhh0 = (const float*)d_in[7];
    const float* wih1 = (const float*)d_in[8];
    const float* whh1 = (const float*)d_in[9];
    const float* bih1 = (const float*)d_in[10];
    const float* bhh1 = (const float*)d_in[11];
    const float* wqkv = (const float*)d_in[12];
    const float* bqkv = (const float*)d_in[13];
    const float* wo   = (const float*)d_in[14];
    const float* bo   = (const float*)d_in[15];
    const float* w1   = (const float*)d_in[16];
    const float* b1   = (const float*)d_in[17];
    const float* w2   = (const float*)d_in[18];
    const float* b2   = (const float*)d_in[19];
    const float* ln1g = (const float*)d_in[20];
    const float* ln1b = (const float*)d_in[21];
    const float* ln2g = (const float*)d_in[22];
    const float* ln2b = (const float*)d_in[23];
    float* out = (float*)d_out;

    float *seg, *gi, *gh, *h, *y0, *y1, *xn, *qkv, *att, *o, *ff;
    cudaGetSymbolAddress((void**)&seg, g_seg);
    cudaGetSymbolAddress((void**)&gi,  g_gi);
    cudaGetSymbolAddress((void**)&gh,  g_gh);
    cudaGetSymbolAddress((void**)&h,   g_h);
    cudaGetSymbolAddress((void**)&y0,  g_y0);
    cudaGetSymbolAddress((void**)&y1,  g_y1);
    cudaGetSymbolAddress((void**)&xn,  g_xn);
    cudaGetSymbolAddress((void**)&qkv, g_qkv);
    cudaGetSymbolAddress((void**)&att, g_att);
    cudaGetSymbolAddress((void**)&o,   g_o);
    cudaGetSymbolAddress((void**)&ff,  g_ff);

    // positional tables + token embed
    sintab_kernel<<<((TT + NWRD) * DIM + 255) / 256, 256>>>();
    embed_kernel<<<(unsigned)(((size_t)NTOT * DIM + 255) / 256), 256>>>(x, emb);

    // ---- GRU layer 0 (both directions batched via grid.z) ----
    run_gemm(GM_PLAIN, seg, wih0, nullptr, gi,
             NTOT, H3, DIM, DIM, DIM, H3,
             2, 1, 0, 0, (long long)H3 * DIM, 0, (long long)NTOT * H3, 0, 0, 1.f);
    run_zero(h, 2ull * NSEG * HID);
    for (int s = 0; s < TT; s++) {
        if (s == 0) run_zero(gh, 2ull * NSEG * H3);
        else run_gemm(GM_PLAIN, h, whh0, nullptr, gh,
                      NSEG, H3, HID, HID, HID, H3,
                      2, 1, (long long)NSEG * HID, 0, (long long)H3 * HID, 0,
                      (long long)NSEG * H3, 0, 0, 1.f);
        gru_gate_kernel<<<(unsigned)((2ull * NSEG * HID + 255) / 256), 256>>>(bih0, bhh0, y0, s);
    }

    // ---- GRU layer 1 (input width 2H) ----
    run_gemm(GM_PLAIN, y0, wih1, nullptr, gi,
             NTOT, H3, 2 * HID, 2 * HID, 2 * HID, H3,
             2, 1, 0, 0, (long long)H3 * 2 * HID, 0, (long long)NTOT * H3, 0, 0, 1.f);
    run_zero(h, 2ull * NSEG * HID);
    for (int s = 0; s < TT; s++) {
        if (s == 0) run_zero(gh, 2ull * NSEG * H3);
        else run_gemm(GM_PLAIN, h, whh1, nullptr, gh,
                      NSEG, H3, HID, HID, HID, H3,
                      2, 1, (long long)NSEG * HID, 0, (long long)H3 * HID, 0,
                      (long long)NSEG * H3, 0, 0, 1.f);
        gru_gate_kernel<<<(unsigned)((2ull * NSEG * HID + 255) / 256), 256>>>(bih1, bhh1, y1, s);
    }

    // ---- word embeddings -> BERT residual stream (lives in d_out) ----
    we_kernel<<<(unsigned)(((size_t)NSEG * DIM + 255) / 256), 256>>>(bemb, out);

    const float qscale = 1.0f / sqrtf((float)DHD);
    for (int l = 0; l < NLAY; l++) {
        // pre-norm attention
        ln_kernel<<<NSEG, 256>>>(out, ln1g + (size_t)l * DIM, ln1b + (size_t)l * DIM, xn);
        run_gemm(GM_BIAS, xn, wqkv + (size_t)l * 3 * DIM * DIM, bqkv + (size_t)l * 3 * DIM, qkv,
                 NSEG, DIM, DIM, DIM, DIM, DIM,
                 3, 1, 0, 0, (long long)DIM * DIM, 0, (long long)NSEG * DIM, 0, DIM, 1.f);
        // scores[b,h,q,k] = q.k / sqrt(dh), batched over 32 (b,h)
        run_gemm(GM_PLAIN, qkv, qkv + (size_t)NSEG * DIM, nullptr, att,
                 NWRD, NWRD, DHD, DIM, DIM, NWRD,
                 BB * NHEAD, NHEAD,
                 (long long)NWRD * DIM, DHD,
                 (long long)NWRD * DIM, DHD,
                 (long long)NHEAD * NWRD * NWRD, (long long)NWRD * NWRD, 0, qscale);
        softmax_kernel<<<(BB * NHEAD * NWRD) / 4, 128>>>(att);
        // o[b,q,h,d] = att @ v   (NN GEMM)
        run_gemm(GM_NN, att, qkv + 2ull * NSEG * DIM, nullptr, o,
                 NWRD, DHD, NWRD, NWRD, DIM, DIM,
                 BB * NHEAD, NHEAD,
                 (long long)NHEAD * NWRD * NWRD, (long long)NWRD * NWRD,
                 (long long)NWRD * DIM, DHD,
                 (long long)NWRD * DIM, DHD, 0, 1.f);
        // h += o @ Wo^T + bo
        run_gemm(GM_ACCBIAS, o, wo + (size_t)l * DIM * DIM, bo + (size_t)l * DIM, out,
                 NSEG, DIM, DIM, DIM, DIM, DIM,
                 1, 1, 0, 0, 0, 0, 0, 0, 0, 1.f);
        // pre-norm FF
        ln_kernel<<<NSEG, 256>>>(out, ln2g + (size_t)l * DIM, ln2b + (size_t)l * DIM, xn);
        run_gemm(GM_BIASGELU, xn, w1 + (size_t)l * FFD * DIM, b1 + (size_t)l * FFD, ff,
                 NSEG, FFD, DIM, DIM, DIM, FFD,
                 1, 1, 0, 0, 0, 0, 0, 0, 0, 1.f);
        run_gemm(GM_ACCBIAS, ff, w2 + (size_t)l * DIM * FFD, b2 + (size_t)l * DIM, out,
                 NSEG, DIM, FFD, FFD, FFD, DIM,
                 1, 1, 0, 0, 0, 0, 0, 0, 0, 1.f);
    }
}

// round 2
// speedup vs baseline: 3.3226x; 3.3226x over previous
#include <cuda_runtime.h>
#include <math.h>
#include <stdint.h>

// ---------------- problem constants (fixed shapes for this problem) ----------
constexpr int BB   = 8;      // batch
constexpr int NWRD = 256;    // words per utterance
constexpr int DIM  = 768;    // model dim
constexpr int HID  = 768;    // GRU hidden
constexpr int TT   = 8;      // tokens per word (WLEN)
constexpr int NSEG = BB * NWRD;       // 2048 GRU sequences
constexpr int H3   = 3 * HID;         // 2304
constexpr int NTOT = NSEG * TT;       // 16384 rows for gi GEMMs
constexpr int FFD  = 3072;
constexpr int NHEAD= 4;
constexpr int DHD  = 192;
constexpr int NLAY = 3;

// ---------------- scratch (device globals; no cudaMalloc allowed) ------------
__device__ float g_s8  [TT * DIM];
__device__ float g_s256[NWRD * DIM];
__device__ float g_seg [(size_t)NTOT * DIM];
__device__ float g_gi  [2ull * NTOT * H3];     // per-direction input projections
__device__ float g_gh  [2ull * NSEG * H3];     // per-step hidden projections
__device__ float g_h   [2ull * NSEG * HID];    // GRU hidden state per dir
__device__ float g_y0  [(size_t)NTOT * 2 * HID];
__device__ float g_y1  [(size_t)NTOT * 2 * HID];
__device__ float g_xn  [(size_t)NSEG * DIM];
__device__ float g_qkv [3ull * NSEG * DIM];
__device__ float g_att [(size_t)BB * NHEAD * NWRD * NWRD];
__device__ float g_o   [(size_t)NSEG * DIM];
__device__ float g_ff  [(size_t)NSEG * FFD];

// ---------------- small helpers ----------------------------------------------
__device__ __forceinline__ float gelu_f(float x) {
    float x3 = x * x * x;
    return 0.5f * x * (1.f + tanhf(0.7978845608028654f * (x + 0.044715f * x3)));
}
__device__ __forceinline__ float sigmoid_f(float x) {
    return 1.f / (1.f + expf(-x));
}
__device__ __forceinline__ float cvt_tf32(float x) {
    uint32_t u;
    asm("cvt.rna.tf32.f32 %0, %1;" : "=r"(u) : "f"(x));
    return __uint_as_float(u);
}
__device__ __forceinline__ void mma_tf32(float (&d)[4], const uint32_t (&a)[4],
                                         const uint32_t (&b)[2]) {
    asm volatile(
        "mma.sync.aligned.m16n8k8.row.col.f32.tf32.tf32.f32 "
        "{%0,%1,%2,%3}, {%4,%5,%6,%7}, {%8,%9}, {%0,%1,%2,%3};\n"
        : "+f"(d[0]), "+f"(d[1]), "+f"(d[2]), "+f"(d[3])
        : "r"(a[0]), "r"(a[1]), "r"(a[2]), "r"(a[3]), "r"(b[0]), "r"(b[1]));
}

__global__ void zero_kernel(float* p, size_t n) {
    size_t i = (size_t)blockIdx.x * blockDim.x + threadIdx.x;
    if (i < n) p[i] = 0.f;
}

// Sinusoid tables computed in double to match numpy float64 table construction.
__global__ void sintab_kernel() {
    int idx = blockIdx.x * blockDim.x + threadIdx.x;
    const int total = (TT + NWRD) * DIM;
    if (idx >= total) return;
    int p = idx / DIM, d = idx % DIM;
    double e   = (double)(2 * (d / 2)) / (double)DIM;
    double den = pow(10000.0, e);
    int pos    = (p < TT) ? p : (p - TT);
    double ang = (double)pos / den;
    float v = (d & 1) ? (float)cos(ang) : (float)sin(ang);
    if (p < TT) g_s8[p * DIM + d] = v;
    else        g_s256[(p - TT) * DIM + d] = v;
}

// seg[n,t,d] = emb[x[n*8+t], d] + sin8[t,d]
__global__ void embed_kernel(const int* __restrict__ x, const float* __restrict__ emb) {
    size_t idx = (size_t)blockIdx.x * blockDim.x + threadIdx.x;
    if (idx >= (size_t)NTOT * DIM) return;
    int d  = (int)(idx % DIM);
    int nt = (int)(idx / DIM);
    int t  = nt % TT;
    int tok = x[nt];
    g_seg[idx] = emb[(size_t)tok * DIM + d] + g_s8[t * DIM + d];
}

// PyTorch GRU cell gates (r,z,n); batched over dir via index.
__global__ void gru_gate_kernel(const float* __restrict__ bih,
                                const float* __restrict__ bhh,
                                float* __restrict__ y, int step) {
    size_t idx = (size_t)blockIdx.x * blockDim.x + threadIdx.x;
    if (idx >= 2ull * NSEG * HID) return;
    int j   = (int)(idx % HID);
    int n   = (int)((idx / HID) % NSEG);
    int dir = (int)(idx / ((size_t)NSEG * HID));
    int t   = dir ? (TT - 1 - step) : step;

    const float* gp = g_gi + ((size_t)dir * NTOT + (size_t)n * TT + t) * H3;
    const float* hp = g_gh + ((size_t)dir * NSEG + n) * H3;
    const float* bi = bih + (size_t)dir * H3;
    const float* bh = bhh + (size_t)dir * H3;

    float r  = sigmoid_f(gp[j]           + bi[j]           + hp[j]           + bh[j]);
    float z  = sigmoid_f(gp[HID + j]     + bi[HID + j]     + hp[HID + j]     + bh[HID + j]);
    float ng = gp[2 * HID + j] + bi[2 * HID + j] + r * (hp[2 * HID + j] + bh[2 * HID + j]);

    float* hptr = g_h + ((size_t)dir * NSEG + n) * HID + j;
    float hn = (1.f - z) * tanhf(ng) + z * (*hptr);
    *hptr = hn;
    y[((size_t)n * TT + t) * (2 * HID) + (size_t)dir * HID + j] = hn;
}

// we = y1[:,0]+y1[:,-1], summed over direction halves; + bert_emb + sin256
__global__ void we_kernel(const float* __restrict__ bemb, float* __restrict__ out) {
    size_t idx = (size_t)blockIdx.x * blockDim.x + threadIdx.x;
    if (idx >= (size_t)NSEG * DIM) return;
    int d = (int)(idx % DIM);
    int n = (int)(idx / DIM);
    int w = n % NWRD;
    const float* y = g_y1 + (size_t)n * TT * 2 * HID;
    float v = y[d] + y[HID + d]
            + y[(TT - 1) * 2 * HID + d] + y[(TT - 1) * 2 * HID + HID + d];
    out[idx] = v + bemb[idx] + g_s256[(size_t)w * DIM + d];
}

// LayerNorm over 768, block per row, 256 threads (3 elems each)
__global__ void ln_kernel(const float* __restrict__ xin, const float* __restrict__ g,
                          const float* __restrict__ b, float* __restrict__ xo) {
    int row = blockIdx.x;
    const float* xr = xin + (size_t)row * DIM;
    float v[3], s = 0.f, s2 = 0.f;
    #pragma unroll
    for (int i = 0; i < 3; i++) {
        v[i] = xr[threadIdx.x + i * 256];
        s += v[i]; s2 += v[i] * v[i];
    }
    #pragma unroll
    for (int o = 16; o > 0; o >>= 1) {
        s  += __shfl_down_sync(0xffffffffu, s,  o);
        s2 += __shfl_down_sync(0xffffffffu, s2, o);
    }
    __shared__ float sa[8], sc[8];
    int w = threadIdx.x >> 5, l = threadIdx.x & 31;
    if (l == 0) { sa[w] = s; sc[w] = s2; }
    __syncthreads();
    if (threadIdx.x == 0) {
        float ta = 0.f, tc = 0.f;
        #pragma unroll
        for (int i = 0; i < 8; i++) { ta += sa[i]; tc += sc[i]; }
        sa[0] = ta; sc[0] = tc;
    }
    __syncthreads();
    float mean = sa[0] / DIM;
    float var  = sc[0] / DIM - mean * mean;
    float rstd = rsqrtf(var + 1e-6f);
    #pragma unroll
    for (int i = 0; i < 3; i++) {
        int d = threadIdx.x + i * 256;
        xo[(size_t)row * DIM + d] = (v[i] - mean) * rstd * g[d] + b[d];
    }
}

// softmax over 256 keys, one warp per row
__global__ void softmax_kernel(float* __restrict__ att) {
    int row = blockIdx.x * (blockDim.x / 32) + (threadIdx.x >> 5);
    if (row >= BB * NHEAD * NWRD) return;
    int l = threadIdx.x & 31;
    float* p = att + (size_t)row * NWRD;
    float v[8], m = -1e30f;
    #pragma unroll
    for (int i = 0; i < 8; i++) { v[i] = p[l + i * 32]; m = fmaxf(m, v[i]); }
    #pragma unroll
    for (int o = 16; o > 0; o >>= 1) m = fmaxf(m, __shfl_xor_sync(0xffffffffu, m, o));
    float s = 0.f;
    #pragma unroll
    for (int i = 0; i < 8; i++) { v[i] = expf(v[i] - m); s += v[i]; }
    #pragma unroll
    for (int o = 16; o > 0; o >>= 1) s += __shfl_xor_sync(0xffffffffu, s, o);
    float inv = 1.f / s;
    #pragma unroll
    for (int i = 0; i < 8; i++) p[l + i * 32] = v[i] * inv;
}

// ---------------- tf32 tensor-core batched GEMM -------------------------------
// C = act(alpha * A @ op(B) + bias) [+ C]
// BT=true : B is [N,K] row-major (weights, NT).  BT=false: B is [K,N] (NN).
// Block 128x128, BK=16, double-buffered smem with register staging.
// smem layout [row][20] (pad 16->20): conflict-free for float4 stores and
// for the m16n8k8 fragment read pattern (addr = row*20 + k, k in lane&3).
template <bool BT, bool ACC, bool BIAS, bool GELUA>
__global__ void __launch_bounds__(256, 2) tgemm_k(
    const float* __restrict__ A, const float* __restrict__ B,
    const float* __restrict__ bias, float* __restrict__ C,
    int M, int Nc, int K, int lda, int ldb, int ldc,
    int zdiv, long long sA1, long long sA2, long long sB1, long long sB2,
    long long sC1, long long sC2, long long sBias, float alpha)
{
    int z  = blockIdx.z;
    int z1 = z / zdiv, z2 = z % zdiv;
    A += z1 * sA1 + z2 * sA2;
    B += z1 * sB1 + z2 * sB2;
    C += z1 * sC1 + z2 * sC2;
    if (BIAS) bias += z1 * sBias;

    __shared__ float As[2][128 * 20];
    __shared__ float Bs[2][128 * 20];

    const int tid  = threadIdx.x;
    const int lane = tid & 31;
    const int warp = tid >> 5;
    const int wm = warp & 3;        // 4 warps along M, 32 rows each
    const int wn = warp >> 2;       // 2 warps along N, 64 cols each
    const int bm = blockIdx.y * 128, bn = blockIdx.x * 128;
    const int gid = lane >> 2;      // group id 0..7
    const int tig = lane & 3;       // thread in group

    float acc[2][8][4] = {};

    // staging registers
    float4 ra0, ra1, rb0, rb1;

    auto loadA = [&](int kt) {
        int row = tid >> 1, kc = (tid & 1) * 8;
        int gm = bm + row;
        if (gm < M) {
            const float* p = A + (size_t)gm * lda + kt * 16 + kc;
            ra0 = *(const float4*)p;
            ra1 = *(const float4*)(p + 4);
        } else {
            ra0 = make_float4(0.f, 0.f, 0.f, 0.f); ra1 = ra0;
        }
    };
    auto storeA = [&](int buf) {
        int row = tid >> 1, kc = (tid & 1) * 8;
        float4 v0 = make_float4(cvt_tf32(ra0.x), cvt_tf32(ra0.y), cvt_tf32(ra0.z), cvt_tf32(ra0.w));
        float4 v1 = make_float4(cvt_tf32(ra1.x), cvt_tf32(ra1.y), cvt_tf32(ra1.z), cvt_tf32(ra1.w));
        float* s = &As[buf][row * 20 + kc];
        *(float4*)s = v0;
        *(float4*)(s + 4) = v1;
    };
    auto loadB = [&](int kt) {
        if (BT) {
            int row = tid >> 1, kc = (tid & 1) * 8;
            int gn = bn + row;
            if (gn < Nc) {
                const float* p = B + (size_t)gn * ldb + kt * 16 + kc;
                rb0 = *(const float4*)p;
                rb1 = *(const float4*)(p + 4);
            } else {
                rb0 = make_float4(0.f, 0.f, 0.f, 0.f); rb1 = rb0;
            }
        } else {
            // B [K,N]: tile 16x128; thread: k-row = tid>>4, n = (tid&15)*4 (+64)
            int kr = tid >> 4, nq = (tid & 15) * 4;
            int gk = kt * 16 + kr;
            int gn0 = bn + nq, gn1 = bn + nq + 64;
            rb0 = (gn0 < Nc) ? *(const float4*)(B + (size_t)gk * ldb + gn0)
                             : make_float4(0.f, 0.f, 0.f, 0.f);
            rb1 = (gn1 < Nc) ? *(const float4*)(B + (size_t)gk * ldb + gn1)
                             : make_float4(0.f, 0.f, 0.f, 0.f);
        }
    };
    auto storeB = [&](int buf) {
        if (BT) {
            int row = tid >> 1, kc = (tid & 1) * 8;
            float4 v0 = make_float4(cvt_tf32(rb0.x), cvt_tf32(rb0.y), cvt_tf32(rb0.z), cvt_tf32(rb0.w));
            float4 v1 = make_float4(cvt_tf32(rb1.x), cvt_tf32(rb1.y), cvt_tf32(rb1.z), cvt_tf32(rb1.w));
            float* s = &Bs[buf][row * 20 + kc];
            *(float4*)s = v0;
            *(float4*)(s + 4) = v1;
        } else {
            int kr = tid >> 4, nq = (tid & 15) * 4;
            float* s0 = &Bs[buf][nq * 20 + kr];
            s0[0]      = cvt_tf32(rb0.x);
            s0[20]     = cvt_tf32(rb0.y);
            s0[40]     = cvt_tf32(rb0.z);
            s0[60]     = cvt_tf32(rb0.w);
            float* s1 = &Bs[buf][(nq + 64) * 20 + kr];
            s1[0]      = cvt_tf32(rb1.x);
            s1[20]     = cvt_tf32(rb1.y);
            s1[40]     = cvt_tf32(rb1.z);
            s1[60]     = cvt_tf32(rb1.w);
        }
    };

    const int nk = K / 16;
    loadA(0); loadB(0);
    storeA(0); storeB(0);
    __syncthreads();

    for (int kt = 0; kt < nk; kt++) {
        int cur = kt & 1;
        bool more = (kt + 1 < nk);
        if (more) { loadA(kt + 1); loadB(kt + 1); }

        #pragma unroll
        for (int ks = 0; ks < 2; ks++) {
            const int kk = ks * 8;
            uint32_t af[2][4];
            #pragma unroll
            for (int mi = 0; mi < 2; mi++) {
                const float* s = &As[cur][(wm * 32 + mi * 16 + gid) * 20 + kk + tig];
                af[mi][0] = __float_as_uint(s[0]);
                af[mi][1] = __float_as_uint(s[8 * 20]);
                af[mi][2] = __float_as_uint(s[4]);
                af[mi][3] = __float_as_uint(s[8 * 20 + 4]);
            }
            #pragma unroll
            for (int ni = 0; ni < 8; ni++) {
                const float* s = &Bs[cur][(wn * 64 + ni * 8 + gid) * 20 + kk + tig];
                uint32_t bf[2] = { __float_as_uint(s[0]), __float_as_uint(s[4]) };
                mma_tf32(acc[0][ni], af[0], bf);
                mma_tf32(acc[1][ni], af[1], bf);
            }
        }
        if (more) {
            storeA(cur ^ 1); storeB(cur ^ 1);
            __syncthreads();
        }
    }

    // epilogue
    #pragma unroll
    for (int mi = 0; mi < 2; mi++) {
        #pragma unroll
        for (int ni = 0; ni < 8; ni++) {
            int mrow0 = bm + wm * 32 + mi * 16 + gid;
            int ncol0 = bn + wn * 64 + ni * 8 + 2 * tig;
            #pragma unroll
            for (int e = 0; e < 4; e++) {
                int m = mrow0 + (e >> 1) * 8;
                int n = ncol0 + (e & 1);
                if (m >= M || n >= Nc) continue;
                float v = acc[mi][ni][e] * alpha;
                if (BIAS)  v += bias[n];
                if (GELUA) v = gelu_f(v);
                size_t off = (size_t)m * ldc + n;
                if (ACC) C[off] += v; else C[off] = v;
            }
        }
    }
}

// host-side dispatch
enum GemmMode { GM_PLAIN = 0, GM_BIAS = 1, GM_ACCBIAS = 2, GM_BIASGELU = 3, GM_NN = 4 };

static void run_gemm(GemmMode mode,
                     const float* A, const float* B, const float* bias, float* C,
                     int M, int Nc, int K, int lda, int ldb, int ldc,
                     int batch, int zdiv,
                     long long sA1, long long sA2, long long sB1, long long sB2,
                     long long sC1, long long sC2, long long sBias, float alpha)
{
    dim3 grid((Nc + 127) / 128, (M + 127) / 128, batch);
    switch (mode) {
    case GM_PLAIN:
        tgemm_k<true, false, false, false><<<grid, 256>>>(A, B, bias, C, M, Nc, K, lda, ldb, ldc,
            zdiv, sA1, sA2, sB1, sB2, sC1, sC2, sBias, alpha); break;
    case GM_BIAS:
        tgemm_k<true, false, true, false><<<grid, 256>>>(A, B, bias, C, M, Nc, K, lda, ldb, ldc,
            zdiv, sA1, sA2, sB1, sB2, sC1, sC2, sBias, alpha); break;
    case GM_ACCBIAS:
        tgemm_k<true, true, true, false><<<grid, 256>>>(A, B, bias, C, M, Nc, K, lda, ldb, ldc,
            zdiv, sA1, sA2, sB1, sB2, sC1, sC2, sBias, alpha); break;
    case GM_BIASGELU:
        tgemm_k<true, false, true, true><<<grid, 256>>>(A, B, bias, C, M, Nc, K, lda, ldb, ldc,
            zdiv, sA1, sA2, sB1, sB2, sC1, sC2, sBias, alpha); break;
    case GM_NN:
        tgemm_k<false, false, false, false><<<grid, 256>>>(A, B, bias, C, M, Nc, K, lda, ldb, ldc,
            zdiv, sA1, sA2, sB1, sB2, sC1, sC2, sBias, alpha); break;
    }
}

static void run_zero(float* p, size_t n) {
    zero_kernel<<<(unsigned)((n + 255) / 256), 256>>>(p, n);
}

// ---------------- driver ------------------------------------------------------
extern "C" void kernel_launch(void* const* d_in, const int* in_sizes, int n_in,
                              void* d_out, int out_size)
{
    const int*   x    = (const int*)  d_in[0];
    // d_in[1] = gate_for_words (uniform segmentation, unused: WLEN fixed = 8)
    const float* bemb = (const float*)d_in[2];
    const float* emb  = (const float*)d_in[3];
    const float* wih0 = (const float*)d_in[4];
    const float* whh0 = (const float*)d_in[5];
    const float* bih0 = (const float*)d_in[6];
    const float* bhh0 = (const float*)d_in[7];
    const float* wih1 = (const float*)d_in[8];
    const float* whh1 = (const float*)d_in[9];
    const float* bih1 = (const float*)d_in[10];
    const float* bhh1 = (const float*)d_in[11];
    const float* wqkv = (const float*)d_in[12];
    const float* bqkv = (const float*)d_in[13];
    const float* wo   = (const float*)d_in[14];
    const float* bo   = (const float*)d_in[15];
    const float* w1   = (const float*)d_in[16];
    const float* b1   = (const float*)d_in[17];
    const float* w2   = (const float*)d_in[18];
    const float* b2   = (const float*)d_in[19];
    const float* ln1g = (const float*)d_in[20];
    const float* ln1b = (const float*)d_in[21];
    const float* ln2g = (const float*)d_in[22];
    const float* ln2b = (const float*)d_in[23];
    float* out = (float*)d_out;

    float *seg, *gi, *gh, *h, *y0, *y1, *xn, *qkv, *att, *o, *ff;
    cudaGetSymbolAddress((void**)&seg, g_seg);
    cudaGetSymbolAddress((void**)&gi,  g_gi);
    cudaGetSymbolAddress((void**)&gh,  g_gh);
    cudaGetSymbolAddress((void**)&h,   g_h);
    cudaGetSymbolAddress((void**)&y0,  g_y0);
    cudaGetSymbolAddress((void**)&y1,  g_y1);
    cudaGetSymbolAddress((void**)&xn,  g_xn);
    cudaGetSymbolAddress((void**)&qkv, g_qkv);
    cudaGetSymbolAddress((void**)&att, g_att);
    cudaGetSymbolAddress((void**)&o,   g_o);
    cudaGetSymbolAddress((void**)&ff,  g_ff);

    // positional tables + token embed
    sintab_kernel<<<((TT + NWRD) * DIM + 255) / 256, 256>>>();
    embed_kernel<<<(unsigned)(((size_t)NTOT * DIM + 255) / 256), 256>>>(x, emb);

    // ---- GRU layer 0 (both directions batched via grid.z) ----
    run_gemm(GM_PLAIN, seg, wih0, nullptr, gi,
             NTOT, H3, DIM, DIM, DIM, H3,
             2, 1, 0, 0, (long long)H3 * DIM, 0, (long long)NTOT * H3, 0, 0, 1.f);
    run_zero(h, 2ull * NSEG * HID);
    for (int s = 0; s < TT; s++) {
        if (s == 0) run_zero(gh, 2ull * NSEG * H3);
        else run_gemm(GM_PLAIN, h, whh0, nullptr, gh,
                      NSEG, H3, HID, HID, HID, H3,
                      2, 1, (long long)NSEG * HID, 0, (long long)H3 * HID, 0,
                      (long long)NSEG * H3, 0, 0, 1.f);
        gru_gate_kernel<<<(unsigned)((2ull * NSEG * HID + 255) / 256), 256>>>(bih0, bhh0, y0, s);
    }

    // ---- GRU layer 1 (input width 2H) ----
    run_gemm(GM_PLAIN, y0, wih1, nullptr, gi,
             NTOT, H3, 2 * HID, 2 * HID, 2 * HID, H3,
             2, 1, 0, 0, (long long)H3 * 2 * HID, 0, (long long)NTOT * H3, 0, 0, 1.f);
    run_zero(h, 2ull * NSEG * HID);
    for (int s = 0; s < TT; s++) {
        if (s == 0) run_zero(gh, 2ull * NSEG * H3);
        else run_gemm(GM_PLAIN, h, whh1, nullptr, gh,
                      NSEG, H3, HID, HID, HID, H3,
                      2, 1, (long long)NSEG * HID, 0, (long long)H3 * HID, 0,
                      (long long)NSEG * H3, 0, 0, 1.f);
        gru_gate_kernel<<<(unsigned)((2ull * NSEG * HID + 255) / 256), 256>>>(bih1, bhh1, y1, s);
    }

    // ---- word embeddings -> BERT residual stream (lives in d_out) ----
    we_kernel<<<(unsigned)(((size_t)NSEG * DIM + 255) / 256), 256>>>(bemb, out);

    const float qscale = 1.0f / sqrtf((float)DHD);
    for (int l = 0; l < NLAY; l++) {
        // pre-norm attention
        ln_kernel<<<NSEG, 256>>>(out, ln1g + (size_t)l * DIM, ln1b + (size_t)l * DIM, xn);
        run_gemm(GM_BIAS, xn, wqkv + (size_t)l * 3 * DIM * DIM, bqkv + (size_t)l * 3 * DIM, qkv,
                 NSEG, DIM, DIM, DIM, DIM, DIM,
                 3, 1, 0, 0, (long long)DIM * DIM, 0, (long long)NSEG * DIM, 0, DIM, 1.f);
        // scores[b,h,q,k] = q.k / sqrt(dh), batched over 32 (b,h)
        run_gemm(GM_PLAIN, qkv, qkv + (size_t)NSEG * DIM, nullptr, att,
                 NWRD, NWRD, DHD, DIM, DIM, NWRD,
                 BB * NHEAD, NHEAD,
                 (long long)NWRD * DIM, DHD,
                 (long long)NWRD * DIM, DHD,
                 (long long)NHEAD * NWRD * NWRD, (long long)NWRD * NWRD, 0, qscale);
        softmax_kernel<<<(BB * NHEAD * NWRD) / 4, 128>>>(att);
        // o[b,q,h,d] = att @ v   (NN GEMM)
        run_gemm(GM_NN, att, qkv + 2ull * NSEG * DIM, nullptr, o,
                 NWRD, DHD, NWRD, NWRD, DIM, DIM,
                 BB * NHEAD, NHEAD,
                 (long long)NHEAD * NWRD * NWRD, (long long)NWRD * NWRD,
                 (long long)NWRD * DIM, DHD,
                 (long long)NWRD * DIM, DHD, 0, 1.f);
        // h += o @ Wo^T + bo
        run_gemm(GM_ACCBIAS, o, wo + (size_t)l * DIM * DIM, bo + (size_t)l * DIM, out,
                 NSEG, DIM, DIM, DIM, DIM, DIM,
                 1, 1, 0, 0, 0, 0, 0, 0, 0, 1.f);
        // pre-norm FF
        ln_kernel<<<NSEG, 256>>>(out, ln2g + (size_t)l * DIM, ln2b + (size_t)l * DIM, xn);
        run_gemm(GM_BIASGELU, xn, w1 + (size_t)l * FFD * DIM, b1 + (size_t)l * FFD, ff,
                 NSEG, FFD, DIM, DIM, DIM, FFD,
                 1, 1, 0, 0, 0, 0, 0, 0, 0, 1.f);
        run_gemm(GM_ACCBIAS, ff, w2 + (size_t)l * DIM * FFD, b2 + (size_t)l * DIM, out,
                 NSEG, DIM, FFD, FFD, FFD, DIM,
                 1, 1, 0, 0, 0, 0, 0, 0, 0, 1.f);
    }
}

// round 5
// speedup vs baseline: 4.8354x; 1.4553x over previous
#include <cuda_runtime.h>
#include <cuda_fp16.h>
#include <math.h>
#include <stdint.h>

// ---------------- problem constants ----------------
constexpr int BB   = 8;
constexpr int NWRD = 256;
constexpr int DIM  = 768;
constexpr int HID  = 768;
constexpr int TT   = 8;
constexpr int NSEG = BB * NWRD;       // 2048
constexpr int H3   = 3 * HID;         // 2304
constexpr int NTOT = NSEG * TT;       // 16384
constexpr int FFD  = 3072;
constexpr int NHEAD= 4;
constexpr int DHD  = 192;
constexpr int NLAY = 3;

// ---------------- scratch ----------------
__device__ float g_s8  [TT * DIM];
__device__ float g_s256[NWRD * DIM];
__device__ float g_seg [(size_t)NTOT * DIM];
__device__ float g_gi  [2ull * NTOT * H3];
__device__ float g_gh  [2ull * NSEG * H3];
__device__ float g_h   [2ull * NSEG * HID];
__device__ float g_y0  [(size_t)NTOT * 2 * HID];
__device__ float g_y1  [(size_t)NTOT * 2 * HID];
__device__ float g_xn  [(size_t)NSEG * DIM];
__device__ float g_qkv [3ull * NSEG * DIM];
__device__ float g_att [(size_t)BB * NHEAD * NWRD * NWRD];
__device__ float g_o   [(size_t)NSEG * DIM];
__device__ float g_ff  [(size_t)NSEG * FFD];

// ---------------- helpers ----------------
__device__ __forceinline__ float gelu_f(float x) {
    float x3 = x * x * x;
    return 0.5f * x * (1.f + tanhf(0.7978845608028654f * (x + 0.044715f * x3)));
}
__device__ __forceinline__ float sigmoid_f(float x) {
    return 1.f / (1.f + expf(-x));
}
__device__ __forceinline__ uint32_t smem_u32(const void* p) {
    uint32_t a;
    asm("{ .reg .u64 t; cvta.to.shared.u64 t, %1; cvt.u32.u64 %0, t; }" : "=r"(a) : "l"(p));
    return a;
}
__device__ __forceinline__ void ldsm_x4(uint32_t (&r)[4], uint32_t addr) {
    asm volatile("ldmatrix.sync.aligned.m8n8.x4.shared.b16 {%0,%1,%2,%3}, [%4];"
        : "=r"(r[0]), "=r"(r[1]), "=r"(r[2]), "=r"(r[3]) : "r"(addr));
}
__device__ __forceinline__ void mma_f16(float (&d)[4], const uint32_t (&a)[4],
                                        uint32_t b0, uint32_t b1) {
    asm volatile(
        "mma.sync.aligned.m16n8k16.row.col.f32.f16.f16.f32 "
        "{%0,%1,%2,%3}, {%4,%5,%6,%7}, {%8,%9}, {%0,%1,%2,%3};\n"
        : "+f"(d[0]), "+f"(d[1]), "+f"(d[2]), "+f"(d[3])
        : "r"(a[0]), "r"(a[1]), "r"(a[2]), "r"(a[3]), "r"(b0), "r"(b1));
}

__global__ void zero_kernel(float* p, size_t n) {
    size_t i = (size_t)blockIdx.x * blockDim.x + threadIdx.x;
    if (i < n) p[i] = 0.f;
}

__global__ void sintab_kernel() {
    int idx = blockIdx.x * blockDim.x + threadIdx.x;
    const int total = (TT + NWRD) * DIM;
    if (idx >= total) return;
    int p = idx / DIM, d = idx % DIM;
    double e   = (double)(2 * (d / 2)) / (double)DIM;
    double den = pow(10000.0, e);
    int pos    = (p < TT) ? p : (p - TT);
    double ang = (double)pos / den;
    float v = (d & 1) ? (float)cos(ang) : (float)sin(ang);
    if (p < TT) g_s8[p * DIM + d] = v;
    else        g_s256[(p - TT) * DIM + d] = v;
}

__global__ void embed_kernel(const int* __restrict__ x, const float* __restrict__ emb) {
    size_t idx = (size_t)blockIdx.x * blockDim.x + threadIdx.x;
    if (idx >= (size_t)NTOT * DIM) return;
    int d  = (int)(idx % DIM);
    int nt = (int)(idx / DIM);
    int t  = nt % TT;
    int tok = x[nt];
    g_seg[idx] = emb[(size_t)tok * DIM + d] + g_s8[t * DIM + d];
}

// GRU gates, float4-vectorized (r,z,n order, PyTorch cell)
__global__ void gru_gate_kernel(const float* __restrict__ bih,
                                const float* __restrict__ bhh,
                                float* __restrict__ y, int step) {
    const int J4 = HID / 4;  // 192
    size_t idx = (size_t)blockIdx.x * blockDim.x + threadIdx.x;
    if (idx >= 2ull * NSEG * J4) return;
    int j4  = (int)(idx % J4);
    int n   = (int)((idx / J4) % NSEG);
    int dir = (int)(idx / ((size_t)NSEG * J4));
    int t   = dir ? (TT - 1 - step) : step;

    const float4* gp = (const float4*)(g_gi + ((size_t)dir * NTOT + (size_t)n * TT + t) * H3);
    const float4* hp = (const float4*)(g_gh + ((size_t)dir * NSEG + n) * H3);
    const float4* bi = (const float4*)(bih + (size_t)dir * H3);
    const float4* bh = (const float4*)(bhh + (size_t)dir * H3);

    float4 gr = gp[j4],  gz = gp[J4 + j4],  gn = gp[2 * J4 + j4];
    float4 hr = hp[j4],  hz = hp[J4 + j4],  hn4 = hp[2 * J4 + j4];
    float4 br = bi[j4],  bz = bi[J4 + j4],  bn4 = bi[2 * J4 + j4];
    float4 cr = bh[j4],  cz = bh[J4 + j4],  cn4 = bh[2 * J4 + j4];

    float4* hptr = (float4*)(g_h + ((size_t)dir * NSEG + n) * HID) + j4;
    float4 hold = *hptr;
    float4 out;
    {
        float r = sigmoid_f(gr.x + br.x + hr.x + cr.x);
        float z = sigmoid_f(gz.x + bz.x + hz.x + cz.x);
        float ng = gn.x + bn4.x + r * (hn4.x + cn4.x);
        out.x = (1.f - z) * tanhf(ng) + z * hold.x;
    }
    {
        float r = sigmoid_f(gr.y + br.y + hr.y + cr.y);
        float z = sigmoid_f(gz.y + bz.y + hz.y + cz.y);
        float ng = gn.y + bn4.y + r * (hn4.y + cn4.y);
        out.y = (1.f - z) * tanhf(ng) + z * hold.y;
    }
    {
        float r = sigmoid_f(gr.z + br.z + hr.z + cr.z);
        float z = sigmoid_f(gz.z + bz.z + hz.z + cz.z);
        float ng = gn.z + bn4.z + r * (hn4.z + cn4.z);
        out.z = (1.f - z) * tanhf(ng) + z * hold.z;
    }
    {
        float r = sigmoid_f(gr.w + br.w + hr.w + cr.w);
        float z = sigmoid_f(gz.w + bz.w + hz.w + cz.w);
        float ng = gn.w + bn4.w + r * (hn4.w + cn4.w);
        out.w = (1.f - z) * tanhf(ng) + z * hold.w;
    }
    *hptr = out;
    float4* yp = (float4*)(y + ((size_t)n * TT + t) * (2 * HID) + (size_t)dir * HID) + j4;
    *yp = out;
}

__global__ void we_kernel(const float* __restrict__ bemb, float* __restrict__ out) {
    size_t idx = (size_t)blockIdx.x * blockDim.x + threadIdx.x;
    if (idx >= (size_t)NSEG * DIM) return;
    int d = (int)(idx % DIM);
    int n = (int)(idx / DIM);
    int w = n % NWRD;
    const float* y = g_y1 + (size_t)n * TT * 2 * HID;
    float v = y[d] + y[HID + d]
            + y[(TT - 1) * 2 * HID + d] + y[(TT - 1) * 2 * HID + HID + d];
    out[idx] = v + bemb[idx] + g_s256[(size_t)w * DIM + d];
}

__global__ void ln_kernel(const float* __restrict__ xin, const float* __restrict__ g,
                          const float* __restrict__ b, float* __restrict__ xo) {
    int row = blockIdx.x;
    const float* xr = xin + (size_t)row * DIM;
    float v[3], s = 0.f, s2 = 0.f;
    #pragma unroll
    for (int i = 0; i < 3; i++) {
        v[i] = xr[threadIdx.x + i * 256];
        s += v[i]; s2 += v[i] * v[i];
    }
    #pragma unroll
    for (int o = 16; o > 0; o >>= 1) {
        s  += __shfl_down_sync(0xffffffffu, s,  o);
        s2 += __shfl_down_sync(0xffffffffu, s2, o);
    }
    __shared__ float sa[8], sc[8];
    int w = threadIdx.x >> 5, l = threadIdx.x & 31;
    if (l == 0) { sa[w] = s; sc[w] = s2; }
    __syncthreads();
    if (threadIdx.x == 0) {
        float ta = 0.f, tc = 0.f;
        #pragma unroll
        for (int i = 0; i < 8; i++) { ta += sa[i]; tc += sc[i]; }
        sa[0] = ta; sc[0] = tc;
    }
    __syncthreads();
    float mean = sa[0] / DIM;
    float var  = sc[0] / DIM - mean * mean;
    float rstd = rsqrtf(var + 1e-6f);
    #pragma unroll
    for (int i = 0; i < 3; i++) {
        int d = threadIdx.x + i * 256;
        xo[(size_t)row * DIM + d] = (v[i] - mean) * rstd * g[d] + b[d];
    }
}

__global__ void softmax_kernel(float* __restrict__ att) {
    int row = blockIdx.x * (blockDim.x / 32) + (threadIdx.x >> 5);
    if (row >= BB * NHEAD * NWRD) return;
    int l = threadIdx.x & 31;
    float* p = att + (size_t)row * NWRD;
    float v[8], m = -1e30f;
    #pragma unroll
    for (int i = 0; i < 8; i++) { v[i] = p[l + i * 32]; m = fmaxf(m, v[i]); }
    #pragma unroll
    for (int o = 16; o > 0; o >>= 1) m = fmaxf(m, __shfl_xor_sync(0xffffffffu, m, o));
    float s = 0.f;
    #pragma unroll
    for (int i = 0; i < 8; i++) { v[i] = expf(v[i] - m); s += v[i]; }
    #pragma unroll
    for (int o = 16; o > 0; o >>= 1) s += __shfl_xor_sync(0xffffffffu, s, o);
    float inv = 1.f / s;
    #pragma unroll
    for (int i = 0; i < 8; i++) p[l + i * 32] = v[i] * inv;
}

// =====================================================================
// fp16 mma.sync GEMM (fp32 in/out, fp32 accumulate):
//   C = act(alpha * A @ op(B) + bias) [+ C]
// BT=true: B is [N,K] (NT, weights). BT=false: B is [K,N] (NN).
// Block 128x128, BK=16, double-buffered fp16 smem, ldmatrix fragments.
// smem pitch 24 halves (48B): conflict-free for 16B STS rows and for the
// 8-row ldmatrix pattern (bank groups {0,20,8,28,16,4,24,12} mod 32).
// =====================================================================
template <bool BT, bool ACC, bool BIAS, bool GELUA>
__global__ void __launch_bounds__(256, 2) hgemm_k(
    const float* __restrict__ A, const float* __restrict__ B,
    const float* __restrict__ bias, float* __restrict__ C,
    int M, int Nc, int K, int lda, int ldb, int ldc,
    int zdiv, long long sA1, long long sA2, long long sB1, long long sB2,
    long long sC1, long long sC2, long long sBias, float alpha)
{
    int z  = blockIdx.z;
    int z1 = z / zdiv, z2 = z % zdiv;
    A += z1 * sA1 + z2 * sA2;
    B += z1 * sB1 + z2 * sB2;
    C += z1 * sC1 + z2 * sC2;
    if (BIAS) bias += z1 * sBias;

    constexpr int PITCH = 24;                   // halves per row (48B)
    __shared__ __align__(16) __half As[2][128 * PITCH];
    __shared__ __align__(16) __half Bs[2][128 * PITCH];

    const int tid  = threadIdx.x;
    const int lane = tid & 31;
    const int warp = tid >> 5;
    const int wm = warp & 3;        // 4 warps along M, 32 rows each
    const int wn = warp >> 2;       // 2 warps along N, 64 cols each
    const int bm = blockIdx.y * 128, bn = blockIdx.x * 128;
    const int gid = lane >> 2;
    const int tig = lane & 3;

    const uint32_t as_u = smem_u32(As);
    const uint32_t bs_u = smem_u32(Bs);
    // ldmatrix per-lane address pattern (bytes)
    const int a_r = ((lane >> 3) & 1) * 8 + (lane & 7);
    const int a_c = ((lane >> 4) & 1) * 16;
    const int b_r = ((lane >> 4) & 1) * 8 + (lane & 7);
    const int b_c = ((lane >> 3) & 1) * 16;

    float acc[2][8][4] = {};
    float4 ra0, ra1, rb0, rb1;

    auto loadA = [&](int kt) {
        int row = tid >> 1, kc = (tid & 1) * 8;
        int gm = bm + row;
        if (gm < M) {
            const float* p = A + (size_t)gm * lda + kt * 16 + kc;
            ra0 = *(const float4*)p;
            ra1 = *(const float4*)(p + 4);
        } else { ra0 = make_float4(0, 0, 0, 0); ra1 = ra0; }
    };
    auto storeA = [&](int buf) {
        int row = tid >> 1, kc = (tid & 1) * 8;
        __half2 h[4];
        h[0] = __floats2half2_rn(ra0.x, ra0.y);
        h[1] = __floats2half2_rn(ra0.z, ra0.w);
        h[2] = __floats2half2_rn(ra1.x, ra1.y);
        h[3] = __floats2half2_rn(ra1.z, ra1.w);
        *(uint4*)(&As[buf][row * PITCH + kc]) = *(uint4*)h;
    };
    auto loadB = [&](int kt) {
        if (BT) {
            int row = tid >> 1, kc = (tid & 1) * 8;
            int gn = bn + row;
            if (gn < Nc) {
                const float* p = B + (size_t)gn * ldb + kt * 16 + kc;
                rb0 = *(const float4*)p;
                rb1 = *(const float4*)(p + 4);
            } else { rb0 = make_float4(0, 0, 0, 0); rb1 = rb0; }
        } else {
            int kr = tid >> 4, nq = (tid & 15) * 4;
            int gk = kt * 16 + kr;
            int gn0 = bn + nq, gn1 = bn + nq + 64;
            rb0 = (gn0 < Nc) ? *(const float4*)(B + (size_t)gk * ldb + gn0)
                             : make_float4(0, 0, 0, 0);
            rb1 = (gn1 < Nc) ? *(const float4*)(B + (size_t)gk * ldb + gn1)
                             : make_float4(0, 0, 0, 0);
        }
    };
    auto storeB = [&](int buf) {
        if (BT) {
            int row = tid >> 1, kc = (tid & 1) * 8;
            __half2 h[4];
            h[0] = __floats2half2_rn(rb0.x, rb0.y);
            h[1] = __floats2half2_rn(rb0.z, rb0.w);
            h[2] = __floats2half2_rn(rb1.x, rb1.y);
            h[3] = __floats2half2_rn(rb1.z, rb1.w);
            *(uint4*)(&Bs[buf][row * PITCH + kc]) = *(uint4*)h;
        } else {
            int kr = tid >> 4, nq = (tid & 15) * 4;
            __half* s0 = &Bs[buf][nq * PITCH + kr];
            s0[0]         = __float2half_rn(rb0.x);
            s0[PITCH]     = __float2half_rn(rb0.y);
            s0[2 * PITCH] = __float2half_rn(rb0.z);
            s0[3 * PITCH] = __float2half_rn(rb0.w);
            __half* s1 = &Bs[buf][(nq + 64) * PITCH + kr];
            s1[0]         = __float2half_rn(rb1.x);
            s1[PITCH]     = __float2half_rn(rb1.y);
            s1[2 * PITCH] = __float2half_rn(rb1.z);
            s1[3 * PITCH] = __float2half_rn(rb1.w);
        }
    };

    const int nk = K / 16;
    loadA(0); loadB(0);
    storeA(0); storeB(0);
    __syncthreads();

    for (int kt = 0; kt < nk; kt++) {
        int cur = kt & 1;
        bool more = (kt + 1 < nk);
        if (more) { loadA(kt + 1); loadB(kt + 1); }

        const uint32_t abase = as_u + cur * (128 * PITCH * 2);
        const uint32_t bbase = bs_u + cur * (128 * PITCH * 2);
        uint32_t af[2][4];
        #pragma unroll
        for (int mi = 0; mi < 2; mi++)
            ldsm_x4(af[mi], abase + (uint32_t)((wm * 32 + mi * 16 + a_r) * (PITCH * 2) + a_c));
        #pragma unroll
        for (int nj = 0; nj < 4; nj++) {
            uint32_t bf[4];
            ldsm_x4(bf, bbase + (uint32_t)((wn * 64 + nj * 16 + b_r) * (PITCH * 2) + b_c));
            mma_f16(acc[0][2 * nj],     af[0], bf[0], bf[1]);
            mma_f16(acc[0][2 * nj + 1], af[0], bf[2], bf[3]);
            mma_f16(acc[1][2 * nj],     af[1], bf[0], bf[1]);
            mma_f16(acc[1][2 * nj + 1], af[1], bf[2], bf[3]);
        }
        if (more) {
            storeA(cur ^ 1); storeB(cur ^ 1);
            __syncthreads();
        }
    }

    // epilogue (fragment layout: rows gid, gid+8; cols 2tig, 2tig+1)
    #pragma unroll
    for (int mi = 0; mi < 2; mi++) {
        #pragma unroll
        for (int ni = 0; ni < 8; ni++) {
            int mrow0 = bm + wm * 32 + mi * 16 + gid;
            int ncol0 = bn + wn * 64 + ni * 8 + 2 * tig;
            #pragma unroll
            for (int e = 0; e < 4; e++) {
                int m = mrow0 + (e >> 1) * 8;
                int n = ncol0 + (e & 1);
                if (m >= M || n >= Nc) continue;
                float v = acc[mi][ni][e] * alpha;
                if (BIAS)  v += bias[n];
                if (GELUA) v = gelu_f(v);
                size_t off = (size_t)m * ldc + n;
                if (ACC) C[off] += v; else C[off] = v;
            }
        }
    }
}

// host-side dispatch
enum GemmMode { GM_PLAIN = 0, GM_BIAS = 1, GM_ACCBIAS = 2, GM_BIASGELU = 3, GM_NN = 4 };

static void run_gemm(GemmMode mode,
                     const float* A, const float* B, const float* bias, float* C,
                     int M, int Nc, int K, int lda, int ldb, int ldc,
                     int batch, int zdiv,
                     long long sA1, long long sA2, long long sB1, long long sB2,
                     long long sC1, long long sC2, long long sBias, float alpha)
{
    dim3 grid((Nc + 127) / 128, (M + 127) / 128, batch);
    switch (mode) {
    case GM_PLAIN:
        hgemm_k<true, false, false, false><<<grid, 256>>>(A, B, bias, C, M, Nc, K, lda, ldb, ldc,
            zdiv, sA1, sA2, sB1, sB2, sC1, sC2, sBias, alpha); break;
    case GM_BIAS:
        hgemm_k<true, false, true, false><<<grid, 256>>>(A, B, bias, C, M, Nc, K, lda, ldb, ldc,
            zdiv, sA1, sA2, sB1, sB2, sC1, sC2, sBias, alpha); break;
    case GM_ACCBIAS:
        hgemm_k<true, true, true, false><<<grid, 256>>>(A, B, bias, C, M, Nc, K, lda, ldb, ldc,
            zdiv, sA1, sA2, sB1, sB2, sC1, sC2, sBias, alpha); break;
    case GM_BIASGELU:
        hgemm_k<true, false, true, true><<<grid, 256>>>(A, B, bias, C, M, Nc, K, lda, ldb, ldc,
            zdiv, sA1, sA2, sB1, sB2, sC1, sC2, sBias, alpha); break;
    case GM_NN:
        hgemm_k<false, false, false, false><<<grid, 256>>>(A, B, bias, C, M, Nc, K, lda, ldb, ldc,
            zdiv, sA1, sA2, sB1, sB2, sC1, sC2, sBias, alpha); break;
    }
}

static void run_zero(float* p, size_t n) {
    zero_kernel<<<(unsigned)((n + 255) / 256), 256>>>(p, n);
}

// ---------------- driver ------------------------------------------------------
extern "C" void kernel_launch(void* const* d_in, const int* in_sizes, int n_in,
                              void* d_out, int out_size)
{
    const int*   x    = (const int*)  d_in[0];
    // d_in[1] = gate_for_words (uniform segmentation; WLEN fixed = 8)
    const float* bemb = (const float*)d_in[2];
    const float* emb  = (const float*)d_in[3];
    const float* wih0 = (const float*)d_in[4];
    const float* whh0 = (const float*)d_in[5];
    const float* bih0 = (const float*)d_in[6];
    const float* bhh0 = (const float*)d_in[7];
    const float* wih1 = (const float*)d_in[8];
    const float* whh1 = (const float*)d_in[9];
    const float* bih1 = (const float*)d_in[10];
    const float* bhh1 = (const float*)d_in[11];
    const float* wqkv = (const float*)d_in[12];
    const float* bqkv = (const float*)d_in[13];
    const float* wo   = (const float*)d_in[14];
    const float* bo   = (const float*)d_in[15];
    const float* w1   = (const float*)d_in[16];
    const float* b1   = (const float*)d_in[17];
    const float* w2   = (const float*)d_in[18];
    const float* b2   = (const float*)d_in[19];
    const float* ln1g = (const float*)d_in[20];
    const float* ln1b = (const float*)d_in[21];
    const float* ln2g = (const float*)d_in[22];
    const float* ln2b = (const float*)d_in[23];
    float* out = (float*)d_out;

    float *seg, *gi, *gh, *h, *y0, *y1, *xn, *qkv, *att, *o, *ff;
    cudaGetSymbolAddress((void**)&seg, g_seg);
    cudaGetSymbolAddress((void**)&gi,  g_gi);
    cudaGetSymbolAddress((void**)&gh,  g_gh);
    cudaGetSymbolAddress((void**)&h,   g_h);
    cudaGetSymbolAddress((void**)&y0,  g_y0);
    cudaGetSymbolAddress((void**)&y1,  g_y1);
    cudaGetSymbolAddress((void**)&xn,  g_xn);
    cudaGetSymbolAddress((void**)&qkv, g_qkv);
    cudaGetSymbolAddress((void**)&att, g_att);
    cudaGetSymbolAddress((void**)&o,   g_o);
    cudaGetSymbolAddress((void**)&ff,  g_ff);

    sintab_kernel<<<((TT + NWRD) * DIM + 255) / 256, 256>>>();
    embed_kernel<<<(unsigned)(((size_t)NTOT * DIM + 255) / 256), 256>>>(x, emb);

    const unsigned gate_blocks = (unsigned)((2ull * NSEG * (HID / 4) + 255) / 256);

    // ---- GRU layer 0 (both directions batched via grid.z) ----
    run_gemm(GM_PLAIN, seg, wih0, nullptr, gi,
             NTOT, H3, DIM, DIM, DIM, H3,
             2, 1, 0, 0, (long long)H3 * DIM, 0, (long long)NTOT * H3, 0, 0, 1.f);
    run_zero(h, 2ull * NSEG * HID);
    for (int s = 0; s < TT; s++) {
        if (s == 0) run_zero(gh, 2ull * NSEG * H3);
        else run_gemm(GM_PLAIN, h, whh0, nullptr, gh,
                      NSEG, H3, HID, HID, HID, H3,
                      2, 1, (long long)NSEG * HID, 0, (long long)H3 * HID, 0,
                      (long long)NSEG * H3, 0, 0, 1.f);
        gru_gate_kernel<<<gate_blocks, 256>>>(bih0, bhh0, y0, s);
    }

    // ---- GRU layer 1 (input width 2H) ----
    run_gemm(GM_PLAIN, y0, wih1, nullptr, gi,
             NTOT, H3, 2 * HID, 2 * HID, 2 * HID, H3,
             2, 1, 0, 0, (long long)H3 * 2 * HID, 0, (long long)NTOT * H3, 0, 0, 1.f);
    run_zero(h, 2ull * NSEG * HID);
    for (int s = 0; s < TT; s++) {
        if (s == 0) run_zero(gh, 2ull * NSEG * H3);
        else run_gemm(GM_PLAIN, h, whh1, nullptr, gh,
                      NSEG, H3, HID, HID, HID, H3,
                      2, 1, (long long)NSEG * HID, 0, (long long)H3 * HID, 0,
                      (long long)NSEG * H3, 0, 0, 1.f);
        gru_gate_kernel<<<gate_blocks, 256>>>(bih1, bhh1, y1, s);
    }

    // ---- word embeddings -> BERT residual stream (lives in d_out) ----
    we_kernel<<<(unsigned)(((size_t)NSEG * DIM + 255) / 256), 256>>>(bemb, out);

    const float qscale = 1.0f / sqrtf((float)DHD);
    for (int l = 0; l < NLAY; l++) {
        // pre-norm attention
        ln_kernel<<<NSEG, 256>>>(out, ln1g + (size_t)l * DIM, ln1b + (size_t)l * DIM, xn);
        run_gemm(GM_BIAS, xn, wqkv + (size_t)l * 3 * DIM * DIM, bqkv + (size_t)l * 3 * DIM, qkv,
                 NSEG, DIM, DIM, DIM, DIM, DIM,
                 3, 1, 0, 0, (long long)DIM * DIM, 0, (long long)NSEG * DIM, 0, DIM, 1.f);
        // scores[b,h,q,k] = q.k / sqrt(dh), batched over 32 (b,h)
        run_gemm(GM_PLAIN, qkv, qkv + (size_t)NSEG * DIM, nullptr, att,
                 NWRD, NWRD, DHD, DIM, DIM, NWRD,
                 BB * NHEAD, NHEAD,
                 (long long)NWRD * DIM, DHD,
                 (long long)NWRD * DIM, DHD,
                 (long long)NHEAD * NWRD * NWRD, (long long)NWRD * NWRD, 0, qscale);
        softmax_kernel<<<(BB * NHEAD * NWRD) / 4, 128>>>(att);
        // o[b,q,h,d] = att @ v   (NN GEMM)
        run_gemm(GM_NN, att, qkv + 2ull * NSEG * DIM, nullptr, o,
                 NWRD, DHD, NWRD, NWRD, DIM, DIM,
                 BB * NHEAD, NHEAD,
                 (long long)NHEAD * NWRD * NWRD, (long long)NWRD * NWRD,
                 (long long)NWRD * DIM, DHD,
                 (long long)NWRD * DIM, DHD, 0, 1.f);
        // h += o @ Wo^T + bo
        run_gemm(GM_ACCBIAS, o, wo + (size_t)l * DIM * DIM, bo + (size_t)l * DIM, out,
                 NSEG, DIM, DIM, DIM, DIM, DIM,
                 1, 1, 0, 0, 0, 0, 0, 0, 0, 1.f);
        // pre-norm FF
        ln_kernel<<<NSEG, 256>>>(out, ln2g + (size_t)l * DIM, ln2b + (size_t)l * DIM, xn);
        run_gemm(GM_BIASGELU, xn, w1 + (size_t)l * FFD * DIM, b1 + (size_t)l * FFD, ff,
                 NSEG, FFD, DIM, DIM, DIM, FFD,
                 1, 1, 0, 0, 0, 0, 0, 0, 0, 1.f);
        run_gemm(GM_ACCBIAS, ff, w2 + (size_t)l * DIM * FFD, b2 + (size_t)l * DIM, out,
                 NSEG, DIM, FFD, FFD, FFD, DIM,
                 1, 1, 0, 0, 0, 0, 0, 0, 0, 1.f);
    }
}

// round 6
// speedup vs baseline: 6.5910x; 1.3631x over previous
#include <cuda_runtime.h>
#include <cuda_fp16.h>
#include <math.h>
#include <stdint.h>

// ---------------- problem constants ----------------
constexpr int BB   = 8;
constexpr int NWRD = 256;
constexpr int DIM  = 768;
constexpr int HID  = 768;
constexpr int TT   = 8;
constexpr int NSEG = BB * NWRD;       // 2048
constexpr int H3   = 3 * HID;         // 2304
constexpr int NTOT = NSEG * TT;       // 16384
constexpr int FFD  = 3072;
constexpr int NHEAD= 4;
constexpr int DHD  = 192;
constexpr int NLAY = 3;

// ---------------- fp32 scratch ----------------
__device__ float g_s8  [TT * DIM];
__device__ float g_s256[NWRD * DIM];
__device__ float g_gi  [2ull * NTOT * H3];
__device__ float g_gh  [2ull * NSEG * H3];
__device__ float g_h   [2ull * NSEG * HID];
__device__ float g_y1  [(size_t)NTOT * 2 * HID];
__device__ float g_qkv [3ull * NSEG * DIM];
__device__ float g_att [(size_t)BB * NHEAD * NWRD * NWRD];

// ---------------- fp16 scratch ----------------
__device__ __align__(256) __half g_seg16[(size_t)NTOT * DIM];
__device__ __align__(256) __half g_h16  [2ull * NSEG * HID];
__device__ __align__(256) __half g_y016 [(size_t)NTOT * 2 * HID];
__device__ __align__(256) __half g_xn16 [(size_t)NSEG * DIM];
__device__ __align__(256) __half g_qkv16[3ull * NSEG * DIM];
__device__ __align__(256) __half g_o16  [(size_t)NSEG * DIM];
__device__ __align__(256) __half g_ff16 [(size_t)NSEG * FFD];
// fp16 weights
__device__ __align__(256) __half w16_ih0[2 * H3 * DIM];
__device__ __align__(256) __half w16_hh0[2 * H3 * HID];
__device__ __align__(256) __half w16_ih1[2 * H3 * 2 * HID];
__device__ __align__(256) __half w16_hh1[2 * H3 * HID];
__device__ __align__(256) __half w16_qkv[NLAY * 3 * DIM * DIM];
__device__ __align__(256) __half w16_wo [NLAY * DIM * DIM];
__device__ __align__(256) __half w16_w1 [NLAY * FFD * DIM];
__device__ __align__(256) __half w16_w2 [NLAY * DIM * FFD];

// ---------------- helpers ----------------
__device__ __forceinline__ float gelu_f(float x) {
    float x3 = x * x * x;
    return 0.5f * x * (1.f + tanhf(0.7978845608028654f * (x + 0.044715f * x3)));
}
__device__ __forceinline__ float sigmoid_f(float x) {
    return 1.f / (1.f + expf(-x));
}
__device__ __forceinline__ uint32_t smem_u32(const void* p) {
    uint32_t a;
    asm("{ .reg .u64 t; cvta.to.shared.u64 t, %1; cvt.u32.u64 %0, t; }" : "=r"(a) : "l"(p));
    return a;
}
__device__ __forceinline__ void ldsm_x4(uint32_t (&r)[4], uint32_t addr) {
    asm volatile("ldmatrix.sync.aligned.m8n8.x4.shared.b16 {%0,%1,%2,%3}, [%4];"
        : "=r"(r[0]), "=r"(r[1]), "=r"(r[2]), "=r"(r[3]) : "r"(addr));
}
__device__ __forceinline__ void mma_f16(float (&d)[4], const uint32_t (&a)[4],
                                        uint32_t b0, uint32_t b1) {
    asm volatile(
        "mma.sync.aligned.m16n8k16.row.col.f32.f16.f16.f32 "
        "{%0,%1,%2,%3}, {%4,%5,%6,%7}, {%8,%9}, {%0,%1,%2,%3};\n"
        : "+f"(d[0]), "+f"(d[1]), "+f"(d[2]), "+f"(d[3])
        : "r"(a[0]), "r"(a[1]), "r"(a[2]), "r"(a[3]), "r"(b0), "r"(b1));
}
__device__ __forceinline__ void cp16(uint32_t dst, const void* src) {
    asm volatile("cp.async.cg.shared.global [%0], [%1], 16;" :: "r"(dst), "l"(src));
}
#define CP_COMMIT() asm volatile("cp.async.commit_group;" ::: "memory")

// ---------------- small kernels ----------------
__global__ void cvt_kernel(const float* __restrict__ s, __half* __restrict__ d, int n4) {
    int i = blockIdx.x * blockDim.x + threadIdx.x;
    if (i >= n4) return;
    float4 v = ((const float4*)s)[i];
    ((__half2*)d)[2 * i]     = __floats2half2_rn(v.x, v.y);
    ((__half2*)d)[2 * i + 1] = __floats2half2_rn(v.z, v.w);
}

__global__ void sintab_kernel() {
    int idx = blockIdx.x * blockDim.x + threadIdx.x;
    const int total = (TT + NWRD) * DIM;
    if (idx >= total) return;
    int p = idx / DIM, d = idx % DIM;
    double e   = (double)(2 * (d / 2)) / (double)DIM;
    double den = pow(10000.0, e);
    int pos    = (p < TT) ? p : (p - TT);
    double ang = (double)pos / den;
    float v = (d & 1) ? (float)cos(ang) : (float)sin(ang);
    if (p < TT) g_s8[p * DIM + d] = v;
    else        g_s256[(p - TT) * DIM + d] = v;
}

// seg16[n,t,d] = half(emb[x[n*8+t], d] + sin8[t,d]); 4 elems/thread
__global__ void embed_kernel(const int* __restrict__ x, const float* __restrict__ emb) {
    const int D4 = DIM / 4;
    size_t idx = (size_t)blockIdx.x * blockDim.x + threadIdx.x;
    if (idx >= (size_t)NTOT * D4) return;
    int d4 = (int)(idx % D4);
    int nt = (int)(idx / D4);
    int t  = nt % TT;
    int tok = x[nt];
    float4 ev = ((const float4*)(emb + (size_t)tok * DIM))[d4];
    float4 sv = ((const float4*)(g_s8 + t * DIM))[d4];
    __half2 a = __floats2half2_rn(ev.x + sv.x, ev.y + sv.y);
    __half2 b = __floats2half2_rn(ev.z + sv.z, ev.w + sv.w);
    __half2* dst = (__half2*)(g_seg16 + (size_t)nt * DIM) + 2 * d4;
    dst[0] = a; dst[1] = b;
}

// GRU gates. FIRST: h_old=0 and gh=0 (skip loads). YHALF: write y as fp16
// (layer0 feeds next GEMM); else fp32 (layer1, feeds we_kernel).
template <bool FIRST, bool YHALF>
__global__ void gru_gate_kernel(const float* __restrict__ bih,
                                const float* __restrict__ bhh,
                                __half* __restrict__ yh, float* __restrict__ yf,
                                int step) {
    const int J4 = HID / 4;  // 192
    size_t idx = (size_t)blockIdx.x * blockDim.x + threadIdx.x;
    if (idx >= 2ull * NSEG * J4) return;
    int j4  = (int)(idx % J4);
    int n   = (int)((idx / J4) % NSEG);
    int dir = (int)(idx / ((size_t)NSEG * J4));
    int t   = dir ? (TT - 1 - step) : step;

    const float4* gp = (const float4*)(g_gi + ((size_t)dir * NTOT + (size_t)n * TT + t) * H3);
    const float4* bi = (const float4*)(bih + (size_t)dir * H3);
    const float4* bh = (const float4*)(bhh + (size_t)dir * H3);

    float4 gr = gp[j4], gz = gp[J4 + j4], gn = gp[2 * J4 + j4];
    float4 br = bi[j4], bz = bi[J4 + j4], bn4 = bi[2 * J4 + j4];
    float4 cr = bh[j4], cz = bh[J4 + j4], cn4 = bh[2 * J4 + j4];

    float4 hr, hz, hn4, hold;
    if (FIRST) {
        hr = hz = hn4 = hold = make_float4(0.f, 0.f, 0.f, 0.f);
    } else {
        const float4* hp = (const float4*)(g_gh + ((size_t)dir * NSEG + n) * H3);
        hr = hp[j4]; hz = hp[J4 + j4]; hn4 = hp[2 * J4 + j4];
        hold = ((const float4*)(g_h + ((size_t)dir * NSEG + n) * HID))[j4];
    }

    float4 out;
    {
        float r = sigmoid_f(gr.x + br.x + hr.x + cr.x);
        float z = sigmoid_f(gz.x + bz.x + hz.x + cz.x);
        float ng = gn.x + bn4.x + r * (hn4.x + cn4.x);
        out.x = (1.f - z) * tanhf(ng) + z * hold.x;
    }
    {
        float r = sigmoid_f(gr.y + br.y + hr.y + cr.y);
        float z = sigmoid_f(gz.y + bz.y + hz.y + cz.y);
        float ng = gn.y + bn4.y + r * (hn4.y + cn4.y);
        out.y = (1.f - z) * tanhf(ng) + z * hold.y;
    }
    {
        float r = sigmoid_f(gr.z + br.z + hr.z + cr.z);
        float z = sigmoid_f(gz.z + bz.z + hz.z + cz.z);
        float ng = gn.z + bn4.z + r * (hn4.z + cn4.z);
        out.z = (1.f - z) * tanhf(ng) + z * hold.z;
    }
    {
        float r = sigmoid_f(gr.w + br.w + hr.w + cr.w);
        float z = sigmoid_f(gz.w + bz.w + hz.w + cz.w);
        float ng = gn.w + bn4.w + r * (hn4.w + cn4.w);
        out.w = (1.f - z) * tanhf(ng) + z * hold.w;
    }
    ((float4*)(g_h + ((size_t)dir * NSEG + n) * HID))[j4] = out;
    __half2 o0 = __floats2half2_rn(out.x, out.y);
    __half2 o1 = __floats2half2_rn(out.z, out.w);
    {
        __half2* hp16 = (__half2*)(g_h16 + ((size_t)dir * NSEG + n) * HID) + 2 * j4;
        hp16[0] = o0; hp16[1] = o1;
    }
    size_t yoff = ((size_t)n * TT + t) * (2 * HID) + (size_t)dir * HID;
    if (YHALF) {
        __half2* yp = (__half2*)(yh + yoff) + 2 * j4;
        yp[0] = o0; yp[1] = o1;
    } else {
        ((float4*)(yf + yoff))[j4] = out;
    }
}

__global__ void we_kernel(const float* __restrict__ bemb, float* __restrict__ out) {
    size_t idx = (size_t)blockIdx.x * blockDim.x + threadIdx.x;
    if (idx >= (size_t)NSEG * DIM) return;
    int d = (int)(idx % DIM);
    int n = (int)(idx / DIM);
    int w = n % NWRD;
    const float* y = g_y1 + (size_t)n * TT * 2 * HID;
    float v = y[d] + y[HID + d]
            + y[(TT - 1) * 2 * HID + d] + y[(TT - 1) * 2 * HID + HID + d];
    out[idx] = v + bemb[idx] + g_s256[(size_t)w * DIM + d];
}

// LayerNorm over 768 -> fp16 output
__global__ void ln_kernel(const float* __restrict__ xin, const float* __restrict__ g,
                          const float* __restrict__ b, __half* __restrict__ xo) {
    int row = blockIdx.x;
    const float* xr = xin + (size_t)row * DIM;
    float v[3], s = 0.f, s2 = 0.f;
    #pragma unroll
    for (int i = 0; i < 3; i++) {
        v[i] = xr[threadIdx.x + i * 256];
        s += v[i]; s2 += v[i] * v[i];
    }
    #pragma unroll
    for (int o = 16; o > 0; o >>= 1) {
        s  += __shfl_down_sync(0xffffffffu, s,  o);
        s2 += __shfl_down_sync(0xffffffffu, s2, o);
    }
    __shared__ float sa[8], sc[8];
    int w = threadIdx.x >> 5, l = threadIdx.x & 31;
    if (l == 0) { sa[w] = s; sc[w] = s2; }
    __syncthreads();
    if (threadIdx.x == 0) {
        float ta = 0.f, tc = 0.f;
        #pragma unroll
        for (int i = 0; i < 8; i++) { ta += sa[i]; tc += sc[i]; }
        sa[0] = ta; sc[0] = tc;
    }
    __syncthreads();
    float mean = sa[0] / DIM;
    float var  = sc[0] / DIM - mean * mean;
    float rstd = rsqrtf(var + 1e-6f);
    #pragma unroll
    for (int i = 0; i < 3; i++) {
        int d = threadIdx.x + i * 256;
        xo[(size_t)row * DIM + d] = __float2half_rn((v[i] - mean) * rstd * g[d] + b[d]);
    }
}

__global__ void softmax_kernel(float* __restrict__ att) {
    int row = blockIdx.x * (blockDim.x / 32) + (threadIdx.x >> 5);
    if (row >= BB * NHEAD * NWRD) return;
    int l = threadIdx.x & 31;
    float* p = att + (size_t)row * NWRD;
    float v[8], m = -1e30f;
    #pragma unroll
    for (int i = 0; i < 8; i++) { v[i] = p[l + i * 32]; m = fmaxf(m, v[i]); }
    #pragma unroll
    for (int o = 16; o > 0; o >>= 1) m = fmaxf(m, __shfl_xor_sync(0xffffffffu, m, o));
    float s = 0.f;
    #pragma unroll
    for (int i = 0; i < 8; i++) { v[i] = expf(v[i] - m); s += v[i]; }
    #pragma unroll
    for (int o = 16; o > 0; o >>= 1) s += __shfl_xor_sync(0xffffffffu, s, o);
    float inv = 1.f / s;
    #pragma unroll
    for (int i = 0; i < 8; i++) p[l + i * 32] = v[i] * inv;
}

// =====================================================================
// fp16-in GEMM with cp.async 3-stage pipeline:
//   C = act(alpha * A[M,K] @ B[N,K]^T + bias) [+C]
// A,B fp16 row-major (NT). Block 128x128, BK=32, 3 stages, 48KB smem.
// XOR-swizzled 64B rows: conflict-free for cp.async 16B stores and
// ldmatrix reads. Requires M%128==0, N%128==0, K%32==0 (all call sites).
// OUTMODE: 0 = fp32 C, 1 = fp16 Ch, 2 = both.
// =====================================================================
template <int OUTMODE, bool ACC, bool BIAS, bool GELUA>
__global__ void __launch_bounds__(256, 2) h2gemm_k(
    const __half* __restrict__ A, const __half* __restrict__ B,
    const float* __restrict__ bias, float* __restrict__ C, __half* __restrict__ Ch,
    int K, int lda, int ldb, int ldc,
    int zdiv, long long sA1, long long sA2, long long sB1, long long sB2,
    long long sC1, long long sC2, long long sBias, float alpha)
{
    int z  = blockIdx.z;
    int z1 = z / zdiv, z2 = z % zdiv;
    A += z1 * sA1 + z2 * sA2;
    B += z1 * sB1 + z2 * sB2;
    if (OUTMODE != 1) C  += z1 * sC1 + z2 * sC2;
    if (OUTMODE != 0) Ch += z1 * sC1 + z2 * sC2;
    if (BIAS) bias += z1 * sBias;

    __shared__ __align__(16) __half AS[3][128 * 32];
    __shared__ __align__(16) __half BS[3][128 * 32];

    const int tid  = threadIdx.x;
    const int lane = tid & 31;
    const int warp = tid >> 5;
    const int wm = warp & 3;
    const int wn = warp >> 2;
    const int bm = blockIdx.y * 128, bn = blockIdx.x * 128;
    const int gid = lane >> 2;
    const int tig = lane & 3;

    const __half* At = A + (size_t)bm * lda;
    const __half* Bt = B + (size_t)bn * ldb;
    const uint32_t as_u = smem_u32(AS);
    const uint32_t bs_u = smem_u32(BS);

    const int a_r = ((lane >> 3) & 1) * 8 + (lane & 7);
    const int a_k = (lane >> 4) & 1;     // logical k16-chunk for A
    const int b_r = ((lane >> 4) & 1) * 8 + (lane & 7);
    const int b_k = (lane >> 3) & 1;     // logical k16-chunk for B

    const int ld_row = tid & 127;
    const int ld_cb  = (tid >> 7) << 1;  // 0 or 2
    const int sw     = (ld_row >> 1) & 3;
    const uint32_t a_dst0 = as_u + ld_row * 64 + ((ld_cb ^ sw) << 4);
    const uint32_t a_dst1 = as_u + ld_row * 64 + (((ld_cb + 1) ^ sw) << 4);
    const uint32_t b_dst0 = bs_u + ld_row * 64 + ((ld_cb ^ sw) << 4);
    const uint32_t b_dst1 = bs_u + ld_row * 64 + (((ld_cb + 1) ^ sw) << 4);
    const __half* a_srcb = At + (size_t)ld_row * lda + ld_cb * 8;
    const __half* b_srcb = Bt + (size_t)ld_row * ldb + ld_cb * 8;

    auto issue = [&](int kt) {
        int slot = kt - (kt / 3) * 3;
        uint32_t so = slot * 8192;
        const __half* as = a_srcb + kt * 32;
        const __half* bs = b_srcb + kt * 32;
        cp16(a_dst0 + so, as);
        cp16(a_dst1 + so, as + 8);
        cp16(b_dst0 + so, bs);
        cp16(b_dst1 + so, bs + 8);
        CP_COMMIT();
    };

    float acc[2][8][4] = {};
    const int nk = K / 32;

    issue(0); issue(1);
    for (int kt = 0; kt < nk; kt++) {
        if (kt == nk - 1) asm volatile("cp.async.wait_group 0;" ::: "memory");
        else              asm volatile("cp.async.wait_group 1;" ::: "memory");
        __syncthreads();
        if (kt + 2 < nk) issue(kt + 2);

        int slot = kt - (kt / 3) * 3;
        const uint32_t abase = as_u + slot * 8192;
        const uint32_t bbase = bs_u + slot * 8192;
        #pragma unroll
        for (int ks = 0; ks < 2; ks++) {
            uint32_t af[2][4];
            #pragma unroll
            for (int mi = 0; mi < 2; mi++) {
                int r = wm * 32 + mi * 16 + a_r;
                int lc = ks * 2 + a_k;
                ldsm_x4(af[mi], abase + r * 64 + ((lc ^ ((r >> 1) & 3)) << 4));
            }
            #pragma unroll
            for (int nj = 0; nj < 4; nj++) {
                int r = wn * 64 + nj * 16 + b_r;
                int lc = ks * 2 + b_k;
                uint32_t bf[4];
                ldsm_x4(bf, bbase + r * 64 + ((lc ^ ((r >> 1) & 3)) << 4));
                mma_f16(acc[0][2 * nj],     af[0], bf[0], bf[1]);
                mma_f16(acc[0][2 * nj + 1], af[0], bf[2], bf[3]);
                mma_f16(acc[1][2 * nj],     af[1], bf[0], bf[1]);
                mma_f16(acc[1][2 * nj + 1], af[1], bf[2], bf[3]);
            }
        }
    }

    // epilogue: acc[mi][ni] rows (gid, gid+8), cols (2tig, 2tig+1)
    #pragma unroll
    for (int mi = 0; mi < 2; mi++) {
        #pragma unroll
        for (int ni = 0; ni < 8; ni++) {
            int col = bn + wn * 64 + ni * 8 + 2 * tig;
            float b0 = 0.f, b1 = 0.f;
            if (BIAS) { b0 = bias[col]; b1 = bias[col + 1]; }
            #pragma unroll
            for (int p = 0; p < 2; p++) {
                int row = bm + wm * 32 + mi * 16 + gid + p * 8;
                float vx = acc[mi][ni][2 * p]     * alpha;
                float vy = acc[mi][ni][2 * p + 1] * alpha;
                if (BIAS)  { vx += b0; vy += b1; }
                if (GELUA) { vx = gelu_f(vx); vy = gelu_f(vy); }
                size_t off = (size_t)row * ldc + col;
                if (OUTMODE != 1) {
                    float2* cp = (float2*)(C + off);
                    if (ACC) { float2 o = *cp; vx += o.x; vy += o.y; }
                    *cp = make_float2(vx, vy);
                }
                if (OUTMODE != 0)
                    *(__half2*)(Ch + off) = __floats2half2_rn(vx, vy);
            }
        }
    }
}

// ---------------- attV: fp32-in NN GEMM (att @ V), fp16 out ----------------
__global__ void __launch_bounds__(256, 2) attv_k(
    const float* __restrict__ A, const float* __restrict__ B,
    __half* __restrict__ Ch,
    int M, int Nc, int K, int lda, int ldb, int ldc,
    int zdiv, long long sA1, long long sA2, long long sB1, long long sB2,
    long long sC1, long long sC2)
{
    int z  = blockIdx.z;
    int z1 = z / zdiv, z2 = z % zdiv;
    A += z1 * sA1 + z2 * sA2;
    B += z1 * sB1 + z2 * sB2;
    Ch += z1 * sC1 + z2 * sC2;

    constexpr int PITCH = 24;
    __shared__ __align__(16) __half As[2][128 * PITCH];
    __shared__ __align__(16) __half Bs[2][128 * PITCH];

    const int tid  = threadIdx.x;
    const int lane = tid & 31;
    const int warp = tid >> 5;
    const int wm = warp & 3;
    const int wn = warp >> 2;
    const int bm = blockIdx.y * 128, bn = blockIdx.x * 128;
    const int gid = lane >> 2;
    const int tig = lane & 3;

    const uint32_t as_u = smem_u32(As);
    const uint32_t bs_u = smem_u32(Bs);
    const int a_r = ((lane >> 3) & 1) * 8 + (lane & 7);
    const int a_c = ((lane >> 4) & 1) * 16;
    const int b_r = ((lane >> 4) & 1) * 8 + (lane & 7);
    const int b_c = ((lane >> 3) & 1) * 16;

    float acc[2][8][4] = {};
    float4 ra0, ra1, rb0, rb1;

    auto loadA = [&](int kt) {
        int row = tid >> 1, kc = (tid & 1) * 8;
        int gm = bm + row;
        if (gm < M) {
            const float* p = A + (size_t)gm * lda + kt * 16 + kc;
            ra0 = *(const float4*)p;
            ra1 = *(const float4*)(p + 4);
        } else { ra0 = make_float4(0, 0, 0, 0); ra1 = ra0; }
    };
    auto storeA = [&](int buf) {
        int row = tid >> 1, kc = (tid & 1) * 8;
        __half2 h[4];
        h[0] = __floats2half2_rn(ra0.x, ra0.y);
        h[1] = __floats2half2_rn(ra0.z, ra0.w);
        h[2] = __floats2half2_rn(ra1.x, ra1.y);
        h[3] = __floats2half2_rn(ra1.z, ra1.w);
        *(uint4*)(&As[buf][row * PITCH + kc]) = *(uint4*)h;
    };
    auto loadB = [&](int kt) {
        int kr = tid >> 4, nq = (tid & 15) * 4;
        int gk = kt * 16 + kr;
        int gn0 = bn + nq, gn1 = bn + nq + 64;
        rb0 = (gn0 < Nc) ? *(const float4*)(B + (size_t)gk * ldb + gn0)
                         : make_float4(0, 0, 0, 0);
        rb1 = (gn1 < Nc) ? *(const float4*)(B + (size_t)gk * ldb + gn1)
                         : make_float4(0, 0, 0, 0);
    };
    auto storeB = [&](int buf) {
        int kr = tid >> 4, nq = (tid & 15) * 4;
        __half* s0 = &Bs[buf][nq * PITCH + kr];
        s0[0]         = __float2half_rn(rb0.x);
        s0[PITCH]     = __float2half_rn(rb0.y);
        s0[2 * PITCH] = __float2half_rn(rb0.z);
        s0[3 * PITCH] = __float2half_rn(rb0.w);
        __half* s1 = &Bs[buf][(nq + 64) * PITCH + kr];
        s1[0]         = __float2half_rn(rb1.x);
        s1[PITCH]     = __float2half_rn(rb1.y);
        s1[2 * PITCH] = __float2half_rn(rb1.z);
        s1[3 * PITCH] = __float2half_rn(rb1.w);
    };

    const int nk = K / 16;
    loadA(0); loadB(0);
    storeA(0); storeB(0);
    __syncthreads();

    for (int kt = 0; kt < nk; kt++) {
        int cur = kt & 1;
        bool more = (kt + 1 < nk);
        if (more) { loadA(kt + 1); loadB(kt + 1); }

        const uint32_t abase = as_u + cur * (128 * PITCH * 2);
        const uint32_t bbase = bs_u + cur * (128 * PITCH * 2);
        uint32_t af[2][4];
        #pragma unroll
        for (int mi = 0; mi < 2; mi++)
            ldsm_x4(af[mi], abase + (uint32_t)((wm * 32 + mi * 16 + a_r) * (PITCH * 2) + a_c));
        #pragma unroll
        for (int nj = 0; nj < 4; nj++) {
            uint32_t bf[4];
            ldsm_x4(bf, bbase + (uint32_t)((wn * 64 + nj * 16 + b_r) * (PITCH * 2) + b_c));
            mma_f16(acc[0][2 * nj],     af[0], bf[0], bf[1]);
            mma_f16(acc[0][2 * nj + 1], af[0], bf[2], bf[3]);
            mma_f16(acc[1][2 * nj],     af[1], bf[0], bf[1]);
            mma_f16(acc[1][2 * nj + 1], af[1], bf[2], bf[3]);
        }
        if (more) {
            storeA(cur ^ 1); storeB(cur ^ 1);
            __syncthreads();
        }
    }
    #pragma unroll
    for (int mi = 0; mi < 2; mi++) {
        #pragma unroll
        for (int ni = 0; ni < 8; ni++) {
            int mrow0 = bm + wm * 32 + mi * 16 + gid;
            int ncol0 = bn + wn * 64 + ni * 8 + 2 * tig;
            #pragma unroll
            for (int e = 0; e < 4; e++) {
                int m = mrow0 + (e >> 1) * 8;
                int n = ncol0 + (e & 1);
                if (m >= M || n >= Nc) continue;
                Ch[(size_t)m * ldc + n] = __float2half_rn(acc[mi][ni][e]);
            }
        }
    }
}

// ---------------- host-side dispatch ----------------
enum GemmMode { GM_PLAIN = 0, GM_BOTH_BIAS = 1, GM_ACCBIAS = 2, GM_GELU16 = 3 };

static void run_h2(GemmMode mode,
                   const __half* A, const __half* B, const float* bias,
                   float* C, __half* Ch,
                   int M, int N, int K, int lda, int ldb, int ldc,
                   int batch, int zdiv,
                   long long sA1, long long sA2, long long sB1, long long sB2,
                   long long sC1, long long sC2, long long sBias, float alpha)
{
    dim3 grid(N / 128, M / 128, batch);
    switch (mode) {
    case GM_PLAIN:
        h2gemm_k<0, false, false, false><<<grid, 256>>>(A, B, bias, C, Ch, K, lda, ldb, ldc,
            zdiv, sA1, sA2, sB1, sB2, sC1, sC2, sBias, alpha); break;
    case GM_BOTH_BIAS:
        h2gemm_k<2, false, true, false><<<grid, 256>>>(A, B, bias, C, Ch, K, lda, ldb, ldc,
            zdiv, sA1, sA2, sB1, sB2, sC1, sC2, sBias, alpha); break;
    case GM_ACCBIAS:
        h2gemm_k<0, true, true, false><<<grid, 256>>>(A, B, bias, C, Ch, K, lda, ldb, ldc,
            zdiv, sA1, sA2, sB1, sB2, sC1, sC2, sBias, alpha); break;
    case GM_GELU16:
        h2gemm_k<1, false, true, true><<<grid, 256>>>(A, B, bias, C, Ch, K, lda, ldb, ldc,
            zdiv, sA1, sA2, sB1, sB2, sC1, sC2, sBias, alpha); break;
    }
}

static void run_cvt(const float* s, __half* d, size_t n) {
    int n4 = (int)(n / 4);
    cvt_kernel<<<(n4 + 255) / 256, 256>>>(s, d, n4);
}

// ---------------- driver ------------------------------------------------------
extern "C" void kernel_launch(void* const* d_in, const int* in_sizes, int n_in,
                              void* d_out, int out_size)
{
    const int*   x    = (const int*)  d_in[0];
    // d_in[1] = gate_for_words (uniform segmentation; WLEN fixed = 8)
    const float* bemb = (const float*)d_in[2];
    const float* emb  = (const float*)d_in[3];
    const float* wih0 = (const float*)d_in[4];
    const float* whh0 = (const float*)d_in[5];
    const float* bih0 = (const float*)d_in[6];
    const float* bhh0 = (const float*)d_in[7];
    const float* wih1 = (const float*)d_in[8];
    const float* whh1 = (const float*)d_in[9];
    const float* bih1 = (const float*)d_in[10];
    const float* bhh1 = (const float*)d_in[11];
    const float* wqkv = (const float*)d_in[12];
    const float* bqkv = (const float*)d_in[13];
    const float* wo   = (const float*)d_in[14];
    const float* bo   = (const float*)d_in[15];
    const float* w1   = (const float*)d_in[16];
    const float* b1   = (const float*)d_in[17];
    const float* w2   = (const float*)d_in[18];
    const float* b2   = (const float*)d_in[19];
    const float* ln1g = (const float*)d_in[20];
    const float* ln1b = (const float*)d_in[21];
    const float* ln2g = (const float*)d_in[22];
    const float* ln2b = (const float*)d_in[23];
    float* out = (float*)d_out;

    float *gi, *gh, *y1, *qkv, *att;
    __half *seg16, *h16, *y016, *xn16, *qkv16, *o16, *ff16;
    __half *ih0h, *hh0h, *ih1h, *hh1h, *qkvh, *woh, *w1h, *w2h;
    cudaGetSymbolAddress((void**)&gi,  g_gi);
    cudaGetSymbolAddress((void**)&gh,  g_gh);
    cudaGetSymbolAddress((void**)&y1,  g_y1);
    cudaGetSymbolAddress((void**)&qkv, g_qkv);
    cudaGetSymbolAddress((void**)&att, g_att);
    cudaGetSymbolAddress((void**)&seg16, g_seg16);
    cudaGetSymbolAddress((void**)&h16,   g_h16);
    cudaGetSymbolAddress((void**)&y016,  g_y016);
    cudaGetSymbolAddress((void**)&xn16,  g_xn16);
    cudaGetSymbolAddress((void**)&qkv16, g_qkv16);
    cudaGetSymbolAddress((void**)&o16,   g_o16);
    cudaGetSymbolAddress((void**)&ff16,  g_ff16);
    cudaGetSymbolAddress((void**)&ih0h, w16_ih0);
    cudaGetSymbolAddress((void**)&hh0h, w16_hh0);
    cudaGetSymbolAddress((void**)&ih1h, w16_ih1);
    cudaGetSymbolAddress((void**)&hh1h, w16_hh1);
    cudaGetSymbolAddress((void**)&qkvh, w16_qkv);
    cudaGetSymbolAddress((void**)&woh,  w16_wo);
    cudaGetSymbolAddress((void**)&w1h,  w16_w1);
    cudaGetSymbolAddress((void**)&w2h,  w16_w2);

    // weight conversion (fp32 -> fp16), once per launch
    run_cvt(wih0, ih0h, 2ull * H3 * DIM);
    run_cvt(whh0, hh0h, 2ull * H3 * HID);
    run_cvt(wih1, ih1h, 2ull * H3 * 2 * HID);
    run_cvt(whh1, hh1h, 2ull * H3 * HID);
    run_cvt(wqkv, qkvh, (size_t)NLAY * 3 * DIM * DIM);
    run_cvt(wo,   woh,  (size_t)NLAY * DIM * DIM);
    run_cvt(w1,   w1h,  (size_t)NLAY * FFD * DIM);
    run_cvt(w2,   w2h,  (size_t)NLAY * DIM * FFD);

    sintab_kernel<<<((TT + NWRD) * DIM + 255) / 256, 256>>>();
    embed_kernel<<<(unsigned)(((size_t)NTOT * (DIM / 4) + 255) / 256), 256>>>(x, emb);

    const unsigned gate_blocks = (unsigned)((2ull * NSEG * (HID / 4) + 255) / 256);

    // ---- GRU layer 0 ----
    run_h2(GM_PLAIN, seg16, ih0h, nullptr, gi, nullptr,
           NTOT, H3, DIM, DIM, DIM, H3,
           2, 1, 0, 0, (long long)H3 * DIM, 0, (long long)NTOT * H3, 0, 0, 1.f);
    gru_gate_kernel<true, true><<<gate_blocks, 256>>>(bih0, bhh0, y016, nullptr, 0);
    for (int s = 1; s < TT; s++) {
        run_h2(GM_PLAIN, h16, hh0h, nullptr, gh, nullptr,
               NSEG, H3, HID, HID, HID, H3,
               2, 1, (long long)NSEG * HID, 0, (long long)H3 * HID, 0,
               (long long)NSEG * H3, 0, 0, 1.f);
        gru_gate_kernel<false, true><<<gate_blocks, 256>>>(bih0, bhh0, y016, nullptr, s);
    }

    // ---- GRU layer 1 ----
    run_h2(GM_PLAIN, y016, ih1h, nullptr, gi, nullptr,
           NTOT, H3, 2 * HID, 2 * HID, 2 * HID, H3,
           2, 1, 0, 0, (long long)H3 * 2 * HID, 0, (long long)NTOT * H3, 0, 0, 1.f);
    gru_gate_kernel<true, false><<<gate_blocks, 256>>>(bih1, bhh1, nullptr, y1, 0);
    for (int s = 1; s < TT; s++) {
        run_h2(GM_PLAIN, h16, hh1h, nullptr, gh, nullptr,
               NSEG, H3, HID, HID, HID, H3,
               2, 1, (long long)NSEG * HID, 0, (long long)H3 * HID, 0,
               (long long)NSEG * H3, 0, 0, 1.f);
        gru_gate_kernel<false, false><<<gate_blocks, 256>>>(bih1, bhh1, nullptr, y1, s);
    }

    we_kernel<<<(unsigned)(((size_t)NSEG * DIM + 255) / 256), 256>>>(bemb, out);

    const float qscale = 1.0f / sqrtf((float)DHD);
    for (int l = 0; l < NLAY; l++) {
        ln_kernel<<<NSEG, 256>>>(out, ln1g + (size_t)l * DIM, ln1b + (size_t)l * DIM, xn16);
        // QKV: fp32 copy (V for attV) + fp16 copy (Q,K for scores; V unused half)
        run_h2(GM_BOTH_BIAS, xn16, qkvh + (size_t)l * 3 * DIM * DIM,
               bqkv + (size_t)l * 3 * DIM, qkv, qkv16,
               NSEG, DIM, DIM, DIM, DIM, DIM,
               3, 1, 0, 0, (long long)DIM * DIM, 0, (long long)NSEG * DIM, 0, DIM, 1.f);
        // scores
        run_h2(GM_PLAIN, qkv16, qkv16 + (size_t)NSEG * DIM, nullptr, att, nullptr,
               NWRD, NWRD, DHD, DIM, DIM, NWRD,
               BB * NHEAD, NHEAD,
               (long long)NWRD * DIM, DHD,
               (long long)NWRD * DIM, DHD,
               (long long)NHEAD * NWRD * NWRD, (long long)NWRD * NWRD, 0, qscale);
        softmax_kernel<<<(BB * NHEAD * NWRD) / 4, 128>>>(att);
        // attV (fp32 in, fp16 out)
        {
            dim3 grid((DHD + 127) / 128, (NWRD + 127) / 128, BB * NHEAD);
            attv_k<<<grid, 256>>>(att, qkv + 2ull * NSEG * DIM, o16,
                NWRD, DHD, NWRD, NWRD, DIM, DIM,
                NHEAD,
                (long long)NHEAD * NWRD * NWRD, (long long)NWRD * NWRD,
                (long long)NWRD * DIM, DHD,
                (long long)NWRD * DIM, DHD);
        }
        run_h2(GM_ACCBIAS, o16, woh + (size_t)l * DIM * DIM, bo + (size_t)l * DIM,
               out, nullptr,
               NSEG, DIM, DIM, DIM, DIM, DIM,
               1, 1, 0, 0, 0, 0, 0, 0, 0, 1.f);
        ln_kernel<<<NSEG, 256>>>(out, ln2g + (size_t)l * DIM, ln2b + (size_t)l * DIM, xn16);
        run_h2(GM_GELU16, xn16, w1h + (size_t)l * FFD * DIM, b1 + (size_t)l * FFD,
               nullptr, ff16,
               NSEG, FFD, DIM, DIM, DIM, FFD,
               1, 1, 0, 0, 0, 0, 0, 0, 0, 1.f);
        run_h2(GM_ACCBIAS, ff16, w2h + (size_t)l * DIM * FFD, b2 + (size_t)l * DIM,
               out, nullptr,
               NSEG, DIM, FFD, FFD, FFD, DIM,
               1, 1, 0, 0, 0, 0, 0, 0, 0, 1.f);
    }
}

// round 7
// speedup vs baseline: 6.6762x; 1.0129x over previous
#include <cuda_runtime.h>
#include <cuda_fp16.h>
#include <math.h>
#include <stdint.h>

// ---------------- problem constants ----------------
constexpr int BB   = 8;
constexpr int NWRD = 256;
constexpr int DIM  = 768;
constexpr int HID  = 768;
constexpr int TT   = 8;
constexpr int NSEG = BB * NWRD;       // 2048
constexpr int H3   = 3 * HID;         // 2304
constexpr int NTOT = NSEG * TT;       // 16384
constexpr int FFD  = 3072;
constexpr int NHEAD= 4;
constexpr int DHD  = 192;
constexpr int NLAY = 3;

// ---------------- fp32 scratch ----------------
__device__ float g_s8  [TT * DIM];
__device__ float g_s256[NWRD * DIM];
__device__ float g_h   [2ull * NSEG * HID];    // recurrent state (fp32)
__device__ float g_y1  [(size_t)NTOT * 2 * HID];
__device__ float g_qkv [3ull * NSEG * DIM];
__device__ float g_att [(size_t)BB * NHEAD * NWRD * NWRD];

// ---------------- fp16 scratch ----------------
__device__ __align__(256) __half g_gi16 [2ull * NTOT * H3];
__device__ __align__(256) __half g_gh16 [2ull * NSEG * H3];
__device__ __align__(256) __half g_seg16[(size_t)NTOT * DIM];
__device__ __align__(256) __half g_h16  [2ull * NSEG * HID];
__device__ __align__(256) __half g_y016 [(size_t)NTOT * 2 * HID];
__device__ __align__(256) __half g_xn16 [(size_t)NSEG * DIM];
__device__ __align__(256) __half g_qkv16[3ull * NSEG * DIM];
__device__ __align__(256) __half g_o16  [(size_t)NSEG * DIM];
__device__ __align__(256) __half g_ff16 [(size_t)NSEG * FFD];
// fp16 weights
__device__ __align__(256) __half w16_ih0[2 * H3 * DIM];
__device__ __align__(256) __half w16_hh0[2 * H3 * HID];
__device__ __align__(256) __half w16_ih1[2 * H3 * 2 * HID];
__device__ __align__(256) __half w16_hh1[2 * H3 * HID];
__device__ __align__(256) __half w16_qkv[NLAY * 3 * DIM * DIM];
__device__ __align__(256) __half w16_wo [NLAY * DIM * DIM];
__device__ __align__(256) __half w16_w1 [NLAY * FFD * DIM];
__device__ __align__(256) __half w16_w2 [NLAY * DIM * FFD];

// ---------------- helpers ----------------
__device__ __forceinline__ float gelu_f(float x) {
    float x3 = x * x * x;
    return 0.5f * x * (1.f + tanhf(0.7978845608028654f * (x + 0.044715f * x3)));
}
__device__ __forceinline__ float sigmoid_f(float x) {
    return 1.f / (1.f + expf(-x));
}
__device__ __forceinline__ uint32_t smem_u32(const void* p) {
    uint32_t a;
    asm("{ .reg .u64 t; cvta.to.shared.u64 t, %1; cvt.u32.u64 %0, t; }" : "=r"(a) : "l"(p));
    return a;
}
__device__ __forceinline__ void ldsm_x4(uint32_t (&r)[4], uint32_t addr) {
    asm volatile("ldmatrix.sync.aligned.m8n8.x4.shared.b16 {%0,%1,%2,%3}, [%4];"
        : "=r"(r[0]), "=r"(r[1]), "=r"(r[2]), "=r"(r[3]) : "r"(addr));
}
__device__ __forceinline__ void mma_f16(float (&d)[4], const uint32_t (&a)[4],
                                        uint32_t b0, uint32_t b1) {
    asm volatile(
        "mma.sync.aligned.m16n8k16.row.col.f32.f16.f16.f32 "
        "{%0,%1,%2,%3}, {%4,%5,%6,%7}, {%8,%9}, {%0,%1,%2,%3};\n"
        : "+f"(d[0]), "+f"(d[1]), "+f"(d[2]), "+f"(d[3])
        : "r"(a[0]), "r"(a[1]), "r"(a[2]), "r"(a[3]), "r"(b0), "r"(b1));
}
__device__ __forceinline__ void cp16(uint32_t dst, const void* src) {
    asm volatile("cp.async.cg.shared.global [%0], [%1], 16;" :: "r"(dst), "l"(src));
}
#define CP_COMMIT() asm volatile("cp.async.commit_group;" ::: "memory")
__device__ __forceinline__ float4 ld4h(const __half* p) {
    __half2 h0 = ((const __half2*)p)[0];
    __half2 h1 = ((const __half2*)p)[1];
    float2 a = __half22float2(h0), b = __half22float2(h1);
    return make_float4(a.x, a.y, b.x, b.y);
}

// ---------------- merged weight conversion (one launch) ----------------
// sizes in float4 units
constexpr int CV0 = 2 * H3 * DIM / 4;            // ih0
constexpr int CV1 = CV0 + 2 * H3 * HID / 4;      // hh0
constexpr int CV2 = CV1 + 2 * H3 * 2 * HID / 4;  // ih1
constexpr int CV3 = CV2 + 2 * H3 * HID / 4;      // hh1
constexpr int CV4 = CV3 + NLAY * 3 * DIM * DIM / 4;
constexpr int CV5 = CV4 + NLAY * DIM * DIM / 4;
constexpr int CV6 = CV5 + NLAY * FFD * DIM / 4;
constexpr int CV7 = CV6 + NLAY * DIM * FFD / 4;

__global__ void cvt_all_kernel(
    const float* s0, const float* s1, const float* s2, const float* s3,
    const float* s4, const float* s5, const float* s6, const float* s7)
{
    int i = blockIdx.x * blockDim.x + threadIdx.x;
    if (i >= CV7) return;
    const float* s; __half* d; int r;
    if      (i < CV0) { s = s0; d = w16_ih0; r = i; }
    else if (i < CV1) { s = s1; d = w16_hh0; r = i - CV0; }
    else if (i < CV2) { s = s2; d = w16_ih1; r = i - CV1; }
    else if (i < CV3) { s = s3; d = w16_hh1; r = i - CV2; }
    else if (i < CV4) { s = s4; d = w16_qkv; r = i - CV3; }
    else if (i < CV5) { s = s5; d = w16_wo;  r = i - CV4; }
    else if (i < CV6) { s = s6; d = w16_w1;  r = i - CV5; }
    else              { s = s7; d = w16_w2;  r = i - CV6; }
    float4 v = ((const float4*)s)[r];
    ((__half2*)d)[2 * r]     = __floats2half2_rn(v.x, v.y);
    ((__half2*)d)[2 * r + 1] = __floats2half2_rn(v.z, v.w);
}

__global__ void sintab_kernel() {
    int idx = blockIdx.x * blockDim.x + threadIdx.x;
    const int total = (TT + NWRD) * DIM;
    if (idx >= total) return;
    int p = idx / DIM, d = idx % DIM;
    double e   = (double)(2 * (d / 2)) / (double)DIM;
    double den = pow(10000.0, e);
    int pos    = (p < TT) ? p : (p - TT);
    double ang = (double)pos / den;
    float v = (d & 1) ? (float)cos(ang) : (float)sin(ang);
    if (p < TT) g_s8[p * DIM + d] = v;
    else        g_s256[(p - TT) * DIM + d] = v;
}

__global__ void embed_kernel(const int* __restrict__ x, const float* __restrict__ emb) {
    const int D4 = DIM / 4;
    size_t idx = (size_t)blockIdx.x * blockDim.x + threadIdx.x;
    if (idx >= (size_t)NTOT * D4) return;
    int d4 = (int)(idx % D4);
    int nt = (int)(idx / D4);
    int t  = nt % TT;
    int tok = x[nt];
    float4 ev = ((const float4*)(emb + (size_t)tok * DIM))[d4];
    float4 sv = ((const float4*)(g_s8 + t * DIM))[d4];
    __half2 a = __floats2half2_rn(ev.x + sv.x, ev.y + sv.y);
    __half2 b = __floats2half2_rn(ev.z + sv.z, ev.w + sv.w);
    __half2* dst = (__half2*)(g_seg16 + (size_t)nt * DIM) + 2 * d4;
    dst[0] = a; dst[1] = b;
}

// GRU gates (fp16 gi/gh inputs, fp32 state). FIRST: h_old=gh=0.
// YHALF: write y fp16 each step (layer0). else: write y fp32 only t==0||t==TT-1.
template <bool FIRST, bool YHALF>
__global__ void gru_gate_kernel(const float* __restrict__ bih,
                                const float* __restrict__ bhh,
                                __half* __restrict__ yh, float* __restrict__ yf,
                                int step) {
    const int J4 = HID / 4;  // 192
    size_t idx = (size_t)blockIdx.x * blockDim.x + threadIdx.x;
    if (idx >= 2ull * NSEG * J4) return;
    int j4  = (int)(idx % J4);
    int n   = (int)((idx / J4) % NSEG);
    int dir = (int)(idx / ((size_t)NSEG * J4));
    int t   = dir ? (TT - 1 - step) : step;

    const __half* gp = g_gi16 + ((size_t)dir * NTOT + (size_t)n * TT + t) * H3;
    const float4* bi = (const float4*)(bih + (size_t)dir * H3);
    const float4* bh = (const float4*)(bhh + (size_t)dir * H3);

    float4 gr = ld4h(gp + 4 * j4);
    float4 gz = ld4h(gp + HID + 4 * j4);
    float4 gn = ld4h(gp + 2 * HID + 4 * j4);
    float4 br = bi[j4], bz = bi[J4 + j4], bn4 = bi[2 * J4 + j4];
    float4 cr = bh[j4], cz = bh[J4 + j4], cn4 = bh[2 * J4 + j4];

    float4 hr, hz, hn4, hold;
    if (FIRST) {
        hr = hz = hn4 = hold = make_float4(0.f, 0.f, 0.f, 0.f);
    } else {
        const __half* hp = g_gh16 + ((size_t)dir * NSEG + n) * H3;
        hr  = ld4h(hp + 4 * j4);
        hz  = ld4h(hp + HID + 4 * j4);
        hn4 = ld4h(hp + 2 * HID + 4 * j4);
        hold = ((const float4*)(g_h + ((size_t)dir * NSEG + n) * HID))[j4];
    }

    float4 out;
    {
        float r = sigmoid_f(gr.x + br.x + hr.x + cr.x);
        float z = sigmoid_f(gz.x + bz.x + hz.x + cz.x);
        float ng = gn.x + bn4.x + r * (hn4.x + cn4.x);
        out.x = (1.f - z) * tanhf(ng) + z * hold.x;
    }
    {
        float r = sigmoid_f(gr.y + br.y + hr.y + cr.y);
        float z = sigmoid_f(gz.y + bz.y + hz.y + cz.y);
        float ng = gn.y + bn4.y + r * (hn4.y + cn4.y);
        out.y = (1.f - z) * tanhf(ng) + z * hold.y;
    }
    {
        float r = sigmoid_f(gr.z + br.z + hr.z + cr.z);
        float z = sigmoid_f(gz.z + bz.z + hz.z + cz.z);
        float ng = gn.z + bn4.z + r * (hn4.z + cn4.z);
        out.z = (1.f - z) * tanhf(ng) + z * hold.z;
    }
    {
        float r = sigmoid_f(gr.w + br.w + hr.w + cr.w);
        float z = sigmoid_f(gz.w + bz.w + hz.w + cz.w);
        float ng = gn.w + bn4.w + r * (hn4.w + cn4.w);
        out.w = (1.f - z) * tanhf(ng) + z * hold.w;
    }
    ((float4*)(g_h + ((size_t)dir * NSEG + n) * HID))[j4] = out;
    __half2 o0 = __floats2half2_rn(out.x, out.y);
    __half2 o1 = __floats2half2_rn(out.z, out.w);
    {
        __half2* hp16 = (__half2*)(g_h16 + ((size_t)dir * NSEG + n) * HID) + 2 * j4;
        hp16[0] = o0; hp16[1] = o1;
    }
    size_t yoff = ((size_t)n * TT + t) * (2 * HID) + (size_t)dir * HID;
    if (YHALF) {
        __half2* yp = (__half2*)(yh + yoff) + 2 * j4;
        yp[0] = o0; yp[1] = o1;
    } else {
        if (t == 0 || t == TT - 1)
            ((float4*)(yf + yoff))[j4] = out;
    }
}

__global__ void we_kernel(const float* __restrict__ bemb, float* __restrict__ out) {
    size_t idx = (size_t)blockIdx.x * blockDim.x + threadIdx.x;
    if (idx >= (size_t)NSEG * DIM) return;
    int d = (int)(idx % DIM);
    int n = (int)(idx / DIM);
    int w = n % NWRD;
    const float* y = g_y1 + (size_t)n * TT * 2 * HID;
    float v = y[d] + y[HID + d]
            + y[(TT - 1) * 2 * HID + d] + y[(TT - 1) * 2 * HID + HID + d];
    out[idx] = v + bemb[idx] + g_s256[(size_t)w * DIM + d];
}

__global__ void ln_kernel(const float* __restrict__ xin, const float* __restrict__ g,
                          const float* __restrict__ b, __half* __restrict__ xo) {
    int row = blockIdx.x;
    const float* xr = xin + (size_t)row * DIM;
    float v[3], s = 0.f, s2 = 0.f;
    #pragma unroll
    for (int i = 0; i < 3; i++) {
        v[i] = xr[threadIdx.x + i * 256];
        s += v[i]; s2 += v[i] * v[i];
    }
    #pragma unroll
    for (int o = 16; o > 0; o >>= 1) {
        s  += __shfl_down_sync(0xffffffffu, s,  o);
        s2 += __shfl_down_sync(0xffffffffu, s2, o);
    }
    __shared__ float sa[8], sc[8];
    int w = threadIdx.x >> 5, l = threadIdx.x & 31;
    if (l == 0) { sa[w] = s; sc[w] = s2; }
    __syncthreads();
    if (threadIdx.x == 0) {
        float ta = 0.f, tc = 0.f;
        #pragma unroll
        for (int i = 0; i < 8; i++) { ta += sa[i]; tc += sc[i]; }
        sa[0] = ta; sc[0] = tc;
    }
    __syncthreads();
    float mean = sa[0] / DIM;
    float var  = sc[0] / DIM - mean * mean;
    float rstd = rsqrtf(var + 1e-6f);
    #pragma unroll
    for (int i = 0; i < 3; i++) {
        int d = threadIdx.x + i * 256;
        xo[(size_t)row * DIM + d] = __float2half_rn((v[i] - mean) * rstd * g[d] + b[d]);
    }
}

__global__ void softmax_kernel(float* __restrict__ att) {
    int row = blockIdx.x * (blockDim.x / 32) + (threadIdx.x >> 5);
    if (row >= BB * NHEAD * NWRD) return;
    int l = threadIdx.x & 31;
    float* p = att + (size_t)row * NWRD;
    float v[8], m = -1e30f;
    #pragma unroll
    for (int i = 0; i < 8; i++) { v[i] = p[l + i * 32]; m = fmaxf(m, v[i]); }
    #pragma unroll
    for (int o = 16; o > 0; o >>= 1) m = fmaxf(m, __shfl_xor_sync(0xffffffffu, m, o));
    float s = 0.f;
    #pragma unroll
    for (int i = 0; i < 8; i++) { v[i] = expf(v[i] - m); s += v[i]; }
    #pragma unroll
    for (int o = 16; o > 0; o >>= 1) s += __shfl_xor_sync(0xffffffffu, s, o);
    float inv = 1.f / s;
    #pragma unroll
    for (int i = 0; i < 8; i++) p[l + i * 32] = v[i] * inv;
}

// =====================================================================
// fp16-in GEMM, cp.async 3-stage pipeline + register-level fragment
// pipelining: C = act(alpha * A[M,K] @ B[N,K]^T + bias) [+C]
// Block 128x128, BK=32. OUTMODE: 0=fp32, 1=fp16, 2=both.
// Requires M%128==0, N%128==0, K%32==0.
// =====================================================================
template <int OUTMODE, bool ACC, bool BIAS, bool GELUA>
__global__ void __launch_bounds__(256, 2) h2gemm_k(
    const __half* __restrict__ A, const __half* __restrict__ B,
    const float* __restrict__ bias, float* __restrict__ C, __half* __restrict__ Ch,
    int K, int lda, int ldb, int ldc,
    int zdiv, long long sA1, long long sA2, long long sB1, long long sB2,
    long long sC1, long long sC2, long long sBias, float alpha)
{
    int z  = blockIdx.z;
    int z1 = z / zdiv, z2 = z % zdiv;
    A += z1 * sA1 + z2 * sA2;
    B += z1 * sB1 + z2 * sB2;
    if (OUTMODE != 1) C  += z1 * sC1 + z2 * sC2;
    if (OUTMODE != 0) Ch += z1 * sC1 + z2 * sC2;
    if (BIAS) bias += z1 * sBias;

    __shared__ __align__(16) __half AS[3][128 * 32];
    __shared__ __align__(16) __half BS[3][128 * 32];

    const int tid  = threadIdx.x;
    const int lane = tid & 31;
    const int warp = tid >> 5;
    const int wm = warp & 3;
    const int wn = warp >> 2;
    const int bm = blockIdx.y * 128, bn = blockIdx.x * 128;
    const int gid = lane >> 2;
    const int tig = lane & 3;

    const __half* At = A + (size_t)bm * lda;
    const __half* Bt = B + (size_t)bn * ldb;
    const uint32_t as_u = smem_u32(AS);
    const uint32_t bs_u = smem_u32(BS);

    const int a_r = ((lane >> 3) & 1) * 8 + (lane & 7);
    const int a_k = (lane >> 4) & 1;
    const int b_r = ((lane >> 4) & 1) * 8 + (lane & 7);
    const int b_k = (lane >> 3) & 1;

    const int ld_row = tid & 127;
    const int ld_cb  = (tid >> 7) << 1;
    const int sw     = (ld_row >> 1) & 3;
    const uint32_t a_dst0 = as_u + ld_row * 64 + ((ld_cb ^ sw) << 4);
    const uint32_t a_dst1 = as_u + ld_row * 64 + (((ld_cb + 1) ^ sw) << 4);
    const uint32_t b_dst0 = bs_u + ld_row * 64 + ((ld_cb ^ sw) << 4);
    const uint32_t b_dst1 = bs_u + ld_row * 64 + (((ld_cb + 1) ^ sw) << 4);
    const __half* a_srcb = At + (size_t)ld_row * lda + ld_cb * 8;
    const __half* b_srcb = Bt + (size_t)ld_row * ldb + ld_cb * 8;

    auto issue = [&](int kt) {
        int slot = kt - (kt / 3) * 3;
        uint32_t so = slot * 8192;
        const __half* as = a_srcb + kt * 32;
        const __half* bs = b_srcb + kt * 32;
        cp16(a_dst0 + so, as);
        cp16(a_dst1 + so, as + 8);
        cp16(b_dst0 + so, bs);
        cp16(b_dst1 + so, bs + 8);
        CP_COMMIT();
    };
    // fragment loaders (so = slot byte offset)
    auto ldA = [&](uint32_t (&f)[2][4], uint32_t so, int ks) {
        #pragma unroll
        for (int mi = 0; mi < 2; mi++) {
            int r = wm * 32 + mi * 16 + a_r;
            int lc = ks * 2 + a_k;
            ldsm_x4(f[mi], as_u + so + r * 64 + ((lc ^ ((r >> 1) & 3)) << 4));
        }
    };
    auto ldB = [&](uint32_t (&f)[4], uint32_t so, int ks, int nj) {
        int r = wn * 64 + nj * 16 + b_r;
        int lc = ks * 2 + b_k;
        ldsm_x4(f, bs_u + so + r * 64 + ((lc ^ ((r >> 1) & 3)) << 4));
    };

    float acc[2][8][4] = {};
    uint32_t afr[2][2][4];   // [ks][mi]
    uint32_t bfr[2][4];      // rolling
    const int nk = K / 32;

    issue(0); issue(1);
    asm volatile("cp.async.wait_group 1;" ::: "memory");
    __syncthreads();
    ldA(afr[0], 0, 0);
    ldB(bfr[0], 0, 0, 0);

    for (int kt = 0; kt < nk; kt++) {
        const uint32_t so = (uint32_t)(kt - (kt / 3) * 3) * 8192;
        if (kt + 2 < nk) issue(kt + 2);
        #pragma unroll
        for (int ks = 0; ks < 2; ks++) {
            #pragma unroll
            for (int nj = 0; nj < 4; nj++) {
                const int cur = nj & 1;
                if (nj < 3) ldB(bfr[cur ^ 1], so, ks, nj + 1);
                else if (ks == 0) { ldA(afr[1], so, 1); ldB(bfr[cur ^ 1], so, 1, 0); }
                mma_f16(acc[0][2 * nj],     afr[ks][0], bfr[cur][0], bfr[cur][1]);
                mma_f16(acc[0][2 * nj + 1], afr[ks][0], bfr[cur][2], bfr[cur][3]);
                mma_f16(acc[1][2 * nj],     afr[ks][1], bfr[cur][0], bfr[cur][1]);
                mma_f16(acc[1][2 * nj + 1], afr[ks][1], bfr[cur][2], bfr[cur][3]);
            }
        }
        if (kt + 1 < nk) {
            if (kt + 2 < nk) asm volatile("cp.async.wait_group 1;" ::: "memory");
            else             asm volatile("cp.async.wait_group 0;" ::: "memory");
            __syncthreads();
            const uint32_t son = (uint32_t)((kt + 1) - ((kt + 1) / 3) * 3) * 8192;
            ldA(afr[0], son, 0);
            ldB(bfr[0], son, 0, 0);
        }
    }

    // epilogue
    #pragma unroll
    for (int mi = 0; mi < 2; mi++) {
        #pragma unroll
        for (int ni = 0; ni < 8; ni++) {
            int col = bn + wn * 64 + ni * 8 + 2 * tig;
            float b0 = 0.f, b1 = 0.f;
            if (BIAS) { b0 = bias[col]; b1 = bias[col + 1]; }
            #pragma unroll
            for (int p = 0; p < 2; p++) {
                int row = bm + wm * 32 + mi * 16 + gid + p * 8;
                float vx = acc[mi][ni][2 * p]     * alpha;
                float vy = acc[mi][ni][2 * p + 1] * alpha;
                if (BIAS)  { vx += b0; vy += b1; }
                if (GELUA) { vx = gelu_f(vx); vy = gelu_f(vy); }
                size_t off = (size_t)row * ldc + col;
                if (OUTMODE != 1) {
                    float2* cp = (float2*)(C + off);
                    if (ACC) { float2 o = *cp; vx += o.x; vy += o.y; }
                    *cp = make_float2(vx, vy);
                }
                if (OUTMODE != 0)
                    *(__half2*)(Ch + off) = __floats2half2_rn(vx, vy);
            }
        }
    }
}

// ---------------- attV: fp32-in NN GEMM (att @ V), fp16 out ----------------
__global__ void __launch_bounds__(256, 2) attv_k(
    const float* __restrict__ A, const float* __restrict__ B,
    __half* __restrict__ Ch,
    int M, int Nc, int K, int lda, int ldb, int ldc,
    int zdiv, long long sA1, long long sA2, long long sB1, long long sB2,
    long long sC1, long long sC2)
{
    int z  = blockIdx.z;
    int z1 = z / zdiv, z2 = z % zdiv;
    A += z1 * sA1 + z2 * sA2;
    B += z1 * sB1 + z2 * sB2;
    Ch += z1 * sC1 + z2 * sC2;

    constexpr int PITCH = 24;
    __shared__ __align__(16) __half As[2][128 * PITCH];
    __shared__ __align__(16) __half Bs[2][128 * PITCH];

    const int tid  = threadIdx.x;
    const int lane = tid & 31;
    const int warp = tid >> 5;
    const int wm = warp & 3;
    const int wn = warp >> 2;
    const int bm = blockIdx.y * 128, bn = blockIdx.x * 128;
    const int gid = lane >> 2;
    const int tig = lane & 3;

    const uint32_t as_u = smem_u32(As);
    const uint32_t bs_u = smem_u32(Bs);
    const int a_r = ((lane >> 3) & 1) * 8 + (lane & 7);
    const int a_c = ((lane >> 4) & 1) * 16;
    const int b_r = ((lane >> 4) & 1) * 8 + (lane & 7);
    const int b_c = ((lane >> 3) & 1) * 16;

    float acc[2][8][4] = {};
    float4 ra0, ra1, rb0, rb1;

    auto loadA = [&](int kt) {
        int row = tid >> 1, kc = (tid & 1) * 8;
        int gm = bm + row;
        if (gm < M) {
            const float* p = A + (size_t)gm * lda + kt * 16 + kc;
            ra0 = *(const float4*)p;
            ra1 = *(const float4*)(p + 4);
        } else { ra0 = make_float4(0, 0, 0, 0); ra1 = ra0; }
    };
    auto storeA = [&](int buf) {
        int row = tid >> 1, kc = (tid & 1) * 8;
        __half2 h[4];
        h[0] = __floats2half2_rn(ra0.x, ra0.y);
        h[1] = __floats2half2_rn(ra0.z, ra0.w);
        h[2] = __floats2half2_rn(ra1.x, ra1.y);
        h[3] = __floats2half2_rn(ra1.z, ra1.w);
        *(uint4*)(&As[buf][row * PITCH + kc]) = *(uint4*)h;
    };
    auto loadB = [&](int kt) {
        int kr = tid >> 4, nq = (tid & 15) * 4;
        int gk = kt * 16 + kr;
        int gn0 = bn + nq, gn1 = bn + nq + 64;
        rb0 = (gn0 < Nc) ? *(const float4*)(B + (size_t)gk * ldb + gn0)
                         : make_float4(0, 0, 0, 0);
        rb1 = (gn1 < Nc) ? *(const float4*)(B + (size_t)gk * ldb + gn1)
                         : make_float4(0, 0, 0, 0);
    };
    auto storeB = [&](int buf) {
        int kr = tid >> 4, nq = (tid & 15) * 4;
        __half* s0 = &Bs[buf][nq * PITCH + kr];
        s0[0]         = __float2half_rn(rb0.x);
        s0[PITCH]     = __float2half_rn(rb0.y);
        s0[2 * PITCH] = __float2half_rn(rb0.z);
        s0[3 * PITCH] = __float2half_rn(rb0.w);
        __half* s1 = &Bs[buf][(nq + 64) * PITCH + kr];
        s1[0]         = __float2half_rn(rb1.x);
        s1[PITCH]     = __float2half_rn(rb1.y);
        s1[2 * PITCH] = __float2half_rn(rb1.z);
        s1[3 * PITCH] = __float2half_rn(rb1.w);
    };

    const int nk = K / 16;
    loadA(0); loadB(0);
    storeA(0); storeB(0);
    __syncthreads();

    for (int kt = 0; kt < nk; kt++) {
        int cur = kt & 1;
        bool more = (kt + 1 < nk);
        if (more) { loadA(kt + 1); loadB(kt + 1); }

        const uint32_t abase = as_u + cur * (128 * PITCH * 2);
        const uint32_t bbase = bs_u + cur * (128 * PITCH * 2);
        uint32_t af[2][4];
        #pragma unroll
        for (int mi = 0; mi < 2; mi++)
            ldsm_x4(af[mi], abase + (uint32_t)((wm * 32 + mi * 16 + a_r) * (PITCH * 2) + a_c));
        #pragma unroll
        for (int nj = 0; nj < 4; nj++) {
            uint32_t bf[4];
            ldsm_x4(bf, bbase + (uint32_t)((wn * 64 + nj * 16 + b_r) * (PITCH * 2) + b_c));
            mma_f16(acc[0][2 * nj],     af[0], bf[0], bf[1]);
            mma_f16(acc[0][2 * nj + 1], af[0], bf[2], bf[3]);
            mma_f16(acc[1][2 * nj],     af[1], bf[0], bf[1]);
            mma_f16(acc[1][2 * nj + 1], af[1], bf[2], bf[3]);
        }
        if (more) {
            storeA(cur ^ 1); storeB(cur ^ 1);
            __syncthreads();
        }
    }
    #pragma unroll
    for (int mi = 0; mi < 2; mi++) {
        #pragma unroll
        for (int ni = 0; ni < 8; ni++) {
            int mrow0 = bm + wm * 32 + mi * 16 + gid;
            int ncol0 = bn + wn * 64 + ni * 8 + 2 * tig;
            #pragma unroll
            for (int e = 0; e < 4; e++) {
                int m = mrow0 + (e >> 1) * 8;
                int n = ncol0 + (e & 1);
                if (m >= M || n >= Nc) continue;
                Ch[(size_t)m * ldc + n] = __float2half_rn(acc[mi][ni][e]);
            }
        }
    }
}

// ---------------- host-side dispatch ----------------
enum GemmMode { GM_PLAIN = 0, GM_BOTH_BIAS = 1, GM_ACCBIAS = 2, GM_GELU16 = 3, GM_PLAIN16 = 4 };

static void run_h2(GemmMode mode,
                   const __half* A, const __half* B, const float* bias,
                   float* C, __half* Ch,
                   int M, int N, int K, int lda, int ldb, int ldc,
                   int batch, int zdiv,
                   long long sA1, long long sA2, long long sB1, long long sB2,
                   long long sC1, long long sC2, long long sBias, float alpha)
{
    dim3 grid(N / 128, M / 128, batch);
    switch (mode) {
    case GM_PLAIN:
        h2gemm_k<0, false, false, false><<<grid, 256>>>(A, B, bias, C, Ch, K, lda, ldb, ldc,
            zdiv, sA1, sA2, sB1, sB2, sC1, sC2, sBias, alpha); break;
    case GM_PLAIN16:
        h2gemm_k<1, false, false, false><<<grid, 256>>>(A, B, bias, C, Ch, K, lda, ldb, ldc,
            zdiv, sA1, sA2, sB1, sB2, sC1, sC2, sBias, alpha); break;
    case GM_BOTH_BIAS:
        h2gemm_k<2, false, true, false><<<grid, 256>>>(A, B, bias, C, Ch, K, lda, ldb, ldc,
            zdiv, sA1, sA2, sB1, sB2, sC1, sC2, sBias, alpha); break;
    case GM_ACCBIAS:
        h2gemm_k<0, true, true, false><<<grid, 256>>>(A, B, bias, C, Ch, K, lda, ldb, ldc,
            zdiv, sA1, sA2, sB1, sB2, sC1, sC2, sBias, alpha); break;
    case GM_GELU16:
        h2gemm_k<1, false, true, true><<<grid, 256>>>(A, B, bias, C, Ch, K, lda, ldb, ldc,
            zdiv, sA1, sA2, sB1, sB2, sC1, sC2, sBias, alpha); break;
    }
}

// ---------------- driver ------------------------------------------------------
extern "C" void kernel_launch(void* const* d_in, const int* in_sizes, int n_in,
                              void* d_out, int out_size)
{
    const int*   x    = (const int*)  d_in[0];
    // d_in[1] = gate_for_words (uniform segmentation; WLEN fixed = 8)
    const float* bemb = (const float*)d_in[2];
    const float* emb  = (const float*)d_in[3];
    const float* wih0 = (const float*)d_in[4];
    const float* whh0 = (const float*)d_in[5];
    const float* bih0 = (const float*)d_in[6];
    const float* bhh0 = (const float*)d_in[7];
    const float* wih1 = (const float*)d_in[8];
    const float* whh1 = (const float*)d_in[9];
    const float* bih1 = (const float*)d_in[10];
    const float* bhh1 = (const float*)d_in[11];
    const float* wqkv = (const float*)d_in[12];
    const float* bqkv = (const float*)d_in[13];
    const float* wo   = (const float*)d_in[14];
    const float* bo   = (const float*)d_in[15];
    const float* w1   = (const float*)d_in[16];
    const float* b1   = (const float*)d_in[17];
    const float* w2   = (const float*)d_in[18];
    const float* b2   = (const float*)d_in[19];
    const float* ln1g = (const float*)d_in[20];
    const float* ln1b = (const float*)d_in[21];
    const float* ln2g = (const float*)d_in[22];
    const float* ln2b = (const float*)d_in[23];
    float* out = (float*)d_out;

    float *y1, *qkv, *att;
    __half *gi16, *gh16, *seg16, *h16, *y016, *xn16, *qkv16, *o16, *ff16;
    __half *ih0h, *hh0h, *ih1h, *hh1h, *qkvh, *woh, *w1h, *w2h;
    cudaGetSymbolAddress((void**)&y1,  g_y1);
    cudaGetSymbolAddress((void**)&qkv, g_qkv);
    cudaGetSymbolAddress((void**)&att, g_att);
    cudaGetSymbolAddress((void**)&gi16,  g_gi16);
    cudaGetSymbolAddress((void**)&gh16,  g_gh16);
    cudaGetSymbolAddress((void**)&seg16, g_seg16);
    cudaGetSymbolAddress((void**)&h16,   g_h16);
    cudaGetSymbolAddress((void**)&y016,  g_y016);
    cudaGetSymbolAddress((void**)&xn16,  g_xn16);
    cudaGetSymbolAddress((void**)&qkv16, g_qkv16);
    cudaGetSymbolAddress((void**)&o16,   g_o16);
    cudaGetSymbolAddress((void**)&ff16,  g_ff16);
    cudaGetSymbolAddress((void**)&ih0h, w16_ih0);
    cudaGetSymbolAddress((void**)&hh0h, w16_hh0);
    cudaGetSymbolAddress((void**)&ih1h, w16_ih1);
    cudaGetSymbolAddress((void**)&hh1h, w16_hh1);
    cudaGetSymbolAddress((void**)&qkvh, w16_qkv);
    cudaGetSymbolAddress((void**)&woh,  w16_wo);
    cudaGetSymbolAddress((void**)&w1h,  w16_w1);
    cudaGetSymbolAddress((void**)&w2h,  w16_w2);

    // all weight conversions in ONE launch
    cvt_all_kernel<<<(CV7 + 255) / 256, 256>>>(wih0, whh0, wih1, whh1, wqkv, wo, w1, w2);
    sintab_kernel<<<((TT + NWRD) * DIM + 255) / 256, 256>>>();
    embed_kernel<<<(unsigned)(((size_t)NTOT * (DIM / 4) + 255) / 256), 256>>>(x, emb);

    const unsigned gate_blocks = (unsigned)((2ull * NSEG * (HID / 4) + 255) / 256);

    // ---- GRU layer 0 ----
    run_h2(GM_PLAIN16, seg16, ih0h, nullptr, nullptr, gi16,
           NTOT, H3, DIM, DIM, DIM, H3,
           2, 1, 0, 0, (long long)H3 * DIM, 0, (long long)NTOT * H3, 0, 0, 1.f);
    gru_gate_kernel<true, true><<<gate_blocks, 256>>>(bih0, bhh0, y016, nullptr, 0);
    for (int s = 1; s < TT; s++) {
        run_h2(GM_PLAIN16, h16, hh0h, nullptr, nullptr, gh16,
               NSEG, H3, HID, HID, HID, H3,
               2, 1, (long long)NSEG * HID, 0, (long long)H3 * HID, 0,
               (long long)NSEG * H3, 0, 0, 1.f);
        gru_gate_kernel<false, true><<<gate_blocks, 256>>>(bih0, bhh0, y016, nullptr, s);
    }

    // ---- GRU layer 1 ----
    run_h2(GM_PLAIN16, y016, ih1h, nullptr, nullptr, gi16,
           NTOT, H3, 2 * HID, 2 * HID, 2 * HID, H3,
           2, 1, 0, 0, (long long)H3 * 2 * HID, 0, (long long)NTOT * H3, 0, 0, 1.f);
    gru_gate_kernel<true, false><<<gate_blocks, 256>>>(bih1, bhh1, nullptr, y1, 0);
    for (int s = 1; s < TT; s++) {
        run_h2(GM_PLAIN16, h16, hh1h, nullptr, nullptr, gh16,
               NSEG, H3, HID, HID, HID, H3,
               2, 1, (long long)NSEG * HID, 0, (long long)H3 * HID, 0,
               (long long)NSEG * H3, 0, 0, 1.f);
        gru_gate_kernel<false, false><<<gate_blocks, 256>>>(bih1, bhh1, nullptr, y1, s);
    }

    we_kernel<<<(unsigned)(((size_t)NSEG * DIM + 255) / 256), 256>>>(bemb, out);

    const float qscale = 1.0f / sqrtf((float)DHD);
    for (int l = 0; l < NLAY; l++) {
        ln_kernel<<<NSEG, 256>>>(out, ln1g + (size_t)l * DIM, ln1b + (size_t)l * DIM, xn16);
        run_h2(GM_BOTH_BIAS, xn16, qkvh + (size_t)l * 3 * DIM * DIM,
               bqkv + (size_t)l * 3 * DIM, qkv, qkv16,
               NSEG, DIM, DIM, DIM, DIM, DIM,
               3, 1, 0, 0, (long long)DIM * DIM, 0, (long long)NSEG * DIM, 0, DIM, 1.f);
        run_h2(GM_PLAIN, qkv16, qkv16 + (size_t)NSEG * DIM, nullptr, att, nullptr,
               NWRD, NWRD, DHD, DIM, DIM, NWRD,
               BB * NHEAD, NHEAD,
               (long long)NWRD * DIM, DHD,
               (long long)NWRD * DIM, DHD,
               (long long)NHEAD * NWRD * NWRD, (long long)NWRD * NWRD, 0, qscale);
        softmax_kernel<<<(BB * NHEAD * NWRD) / 4, 128>>>(att);
        {
            dim3 grid((DHD + 127) / 128, (NWRD + 127) / 128, BB * NHEAD);
            attv_k<<<grid, 256>>>(att, qkv + 2ull * NSEG * DIM, o16,
                NWRD, DHD, NWRD, NWRD, DIM, DIM,
                NHEAD,
                (long long)NHEAD * NWRD * NWRD, (long long)NWRD * NWRD,
                (long long)NWRD * DIM, DHD,
                (long long)NWRD * DIM, DHD);
        }
        run_h2(GM_ACCBIAS, o16, woh + (size_t)l * DIM * DIM, bo + (size_t)l * DIM,
               out, nullptr,
               NSEG, DIM, DIM, DIM, DIM, DIM,
               1, 1, 0, 0, 0, 0, 0, 0, 0, 1.f);
        ln_kernel<<<NSEG, 256>>>(out, ln2g + (size_t)l * DIM, ln2b + (size_t)l * DIM, xn16);
        run_h2(GM_GELU16, xn16, w1h + (size_t)l * FFD * DIM, b1 + (size_t)l * FFD,
               nullptr, ff16,
               NSEG, FFD, DIM, DIM, DIM, FFD,
               1, 1, 0, 0, 0, 0, 0, 0, 0, 1.f);
        run_h2(GM_ACCBIAS, ff16, w2h + (size_t)l * DIM * FFD, b2 + (size_t)l * DIM,
               out, nullptr,
               NSEG, DIM, FFD, FFD, FFD, DIM,
               1, 1, 0, 0, 0, 0, 0, 0, 0, 1.f);
    }
}